// round 15
// baseline (speedup 1.0000x reference)
#include <cuda_runtime.h>
#include <cuda_fp16.h>
#include <math_constants.h>
#include <cstdint>

// ---------------- scratch (static device globals; no allocation) ------------
__device__ float    d_dist[16 * 1024 * 1024];
__device__ float    d_sq  [16 * 1024];
__device__ int      d_idx [16 * 1024 * 40];
__device__ float    d_pq  [16 * 1024 * 512];
__device__ float    d_wpq [92160];
__device__ unsigned d_gmax[16 * 1024];
// fp16-split planes (packed half2 words, k-pairs)
__device__ uint32_t d_ah[16 * 1024 * 64], d_al[16 * 1024 * 64];   // layer input (C<=128)
__device__ uint32_t d_wh[46080],          d_wl[46080];            // wpq
__device__ uint32_t d_fh[1024 * 256],     d_fl[1024 * 256];       // wf
__device__ uint32_t d_ch[16 * 1024 * 256], d_cl[16 * 1024 * 256]; // full cat

static __device__ __forceinline__ unsigned encf(float v) {
    unsigned u = __float_as_uint(v);
    return (u & 0x80000000u) ? ~u : (u | 0x80000000u);
}
static __device__ __forceinline__ void hsplit2(float a, float b,
                                               uint32_t& h, uint32_t& l) {
    __half ha = __float2half_rn(a), hb = __float2half_rn(b);
    __half la = __float2half_rn(a - __half2float(ha));
    __half lb = __float2half_rn(b - __half2float(hb));
    __half2 H = __halves2half2(ha, hb), L = __halves2half2(la, lb);
    h = *(uint32_t*)&H;
    l = *(uint32_t*)&L;
}
static __device__ __forceinline__ void mma_f16(float* c, uint32_t a0, uint32_t a1,
                                               uint32_t a2, uint32_t a3,
                                               uint32_t b0, uint32_t b1) {
    asm volatile(
        "mma.sync.aligned.m16n8k16.row.col.f32.f16.f16.f32 "
        "{%0,%1,%2,%3}, {%4,%5,%6,%7}, {%8,%9}, {%0,%1,%2,%3};"
        : "+f"(c[0]), "+f"(c[1]), "+f"(c[2]), "+f"(c[3])
        : "r"(a0), "r"(a1), "r"(a2), "r"(a3), "r"(b0), "r"(b1));
}

static constexpr int KSW   = 128 * 12;
static constexpr int PLW   = 2 * KSW;
static constexpr int HSMEM = 4 * PLW * 4;   // 49152 bytes

// ---------------- weight conversion ------------------------------------------
__global__ void cvt1d_h(const float* __restrict__ src, uint32_t* __restrict__ hi,
                        uint32_t* __restrict__ lo, int n4)
{
    int i = blockIdx.x * 256 + threadIdx.x;
    if (i >= n4) return;
    float4 v = ((const float4*)src)[i];
    uint2 h, l;
    hsplit2(v.x, v.y, h.x, l.x);
    hsplit2(v.z, v.w, h.y, l.y);
    ((uint2*)hi)[i] = h;
    ((uint2*)lo)[i] = l;
}

// ============ fp16x3 tensor GEMM: C = A(..xK) * B(NxK)^T ====================
// mode 0: plain store.  mode 1: dist-symmetric (B=A, upper-tri, +mirror).
// mode 2: fused max over rows -> atomicMax(gmax).
__global__ void __launch_bounds__(256, 2)
hgemm(const uint32_t* __restrict__ Ah, const uint32_t* __restrict__ Al,
      int ldaw, long long sA,
      const uint32_t* __restrict__ Bh, const uint32_t* __restrict__ Bl,
      int ldbw,
      const float* __restrict__ sq,
      float* __restrict__ C, int ldc, long long sC,
      int N, int K, int mode, unsigned* __restrict__ gmax)
{
    extern __shared__ uint32_t dsm[];
    uint32_t* sAh = dsm;
    uint32_t* sAl = sAh + PLW;
    uint32_t* sBh = sAl + PLW;
    uint32_t* sBl = sBh + PLW;

    int bz = blockIdx.z;
    Ah += (long long)bz * sA;
    Al += (long long)bz * sA;
    const float* sqb = sq ? sq + (long long)bz * 1024 : nullptr;
    C += (long long)bz * sC;

    int bi, bj;
    if (mode == 1) {
        int nb = N >> 7;
        int p = blockIdx.x;
        bi = 0;
        while (p >= nb - bi) { p -= nb - bi; bi++; }
        bj = bi + p;
    } else { bi = blockIdx.x; bj = blockIdx.y; }
    const int row0 = bi * 128, col0 = bj * 128;

    const uint32_t* Bh2 = (mode == 1) ? Ah : Bh;
    const uint32_t* Bl2 = (mode == 1) ? Al : Bl;
    const int ldb2 = (mode == 1) ? ldaw : ldbw;

    const int tid = threadIdx.x;
    const int wid = tid >> 5, lane = tid & 31;
    const int wr = wid >> 2, wc = wid & 3;
    const int g = lane >> 2, t = lane & 3;

    float acc[4][4][4];
#pragma unroll
    for (int mt = 0; mt < 4; mt++)
#pragma unroll
        for (int nt = 0; nt < 4; nt++)
#pragma unroll
            for (int i = 0; i < 4; i++) acc[mt][nt][i] = 0.f;

    int lrow[2], lw4[2], lso[2];
    size_t loa[2], lob[2];
#pragma unroll
    for (int i = 0; i < 2; i++) {
        int id4 = i * 256 + tid;
        lrow[i] = id4 >> 2;
        lw4[i] = id4 & 3;
        int ks = lw4[i] >> 1, wi = (lw4[i] & 1) * 4;
        lso[i] = ks * KSW + lrow[i] * 12 + wi;
        loa[i] = (size_t)(row0 + lrow[i]) * ldaw + lw4[i] * 4;
        lob[i] = (size_t)(col0 + lrow[i]) * ldb2 + lw4[i] * 4;
    }

    uint4 pah[2], pal[2], pbh[2], pbl[2];
    const int nch = K >> 5;

#pragma unroll
    for (int i = 0; i < 2; i++) {
        pah[i] = *(const uint4*)&Ah[loa[i]];
        pal[i] = *(const uint4*)&Al[loa[i]];
        pbh[i] = *(const uint4*)&Bh2[lob[i]];
        pbl[i] = *(const uint4*)&Bl2[lob[i]];
    }
#pragma unroll
    for (int i = 0; i < 2; i++) {
        *(uint4*)&sAh[lso[i]] = pah[i];
        *(uint4*)&sAl[lso[i]] = pal[i];
        *(uint4*)&sBh[lso[i]] = pbh[i];
        *(uint4*)&sBl[lso[i]] = pbl[i];
    }
    __syncthreads();

    for (int ch = 0; ch < nch; ch++) {
        if (ch + 1 < nch) {
            const int k1 = (ch + 1) * 16;
#pragma unroll
            for (int i = 0; i < 2; i++) {
                pah[i] = *(const uint4*)&Ah[loa[i] + k1];
                pal[i] = *(const uint4*)&Al[loa[i] + k1];
                pbh[i] = *(const uint4*)&Bh2[lob[i] + k1];
                pbl[i] = *(const uint4*)&Bl2[lob[i] + k1];
            }
        }

#pragma unroll
        for (int ks = 0; ks < 2; ks++) {
            const uint32_t* pAh = sAh + ks * KSW;
            const uint32_t* pAl = sAl + ks * KSW;
            const uint32_t* pBh = sBh + ks * KSW;
            const uint32_t* pBl = sBl + ks * KSW;

            uint32_t bh0[4], bh1[4], bl0[4], bl1[4];
#pragma unroll
            for (int nt = 0; nt < 4; nt++) {
                int nb_ = wc * 32 + nt * 8 + g;
                bh0[nt] = pBh[nb_ * 12 + t];
                bh1[nt] = pBh[nb_ * 12 + 4 + t];
                bl0[nt] = pBl[nb_ * 12 + t];
                bl1[nt] = pBl[nb_ * 12 + 4 + t];
            }
            uint32_t a[4][4];
#pragma unroll
            for (int mt = 0; mt < 4; mt++) {
                int rb = wr * 64 + mt * 16 + g;
                a[mt][0] = pAh[rb * 12 + t];
                a[mt][1] = pAh[(rb + 8) * 12 + t];
                a[mt][2] = pAh[rb * 12 + 4 + t];
                a[mt][3] = pAh[(rb + 8) * 12 + 4 + t];
            }
#pragma unroll
            for (int nt = 0; nt < 4; nt++)
#pragma unroll
                for (int mt = 0; mt < 4; mt++) {
                    mma_f16(acc[mt][nt], a[mt][0], a[mt][1], a[mt][2], a[mt][3],
                            bh0[nt], bh1[nt]);
                    mma_f16(acc[mt][nt], a[mt][0], a[mt][1], a[mt][2], a[mt][3],
                            bl0[nt], bl1[nt]);
                }
#pragma unroll
            for (int mt = 0; mt < 4; mt++) {
                int rb = wr * 64 + mt * 16 + g;
                a[mt][0] = pAl[rb * 12 + t];
                a[mt][1] = pAl[(rb + 8) * 12 + t];
                a[mt][2] = pAl[rb * 12 + 4 + t];
                a[mt][3] = pAl[(rb + 8) * 12 + 4 + t];
            }
#pragma unroll
            for (int nt = 0; nt < 4; nt++)
#pragma unroll
                for (int mt = 0; mt < 4; mt++)
                    mma_f16(acc[mt][nt], a[mt][0], a[mt][1], a[mt][2], a[mt][3],
                            bh0[nt], bh1[nt]);
        }
        __syncthreads();
        if (ch + 1 < nch) {
#pragma unroll
            for (int i = 0; i < 2; i++) {
                *(uint4*)&sAh[lso[i]] = pah[i];
                *(uint4*)&sAl[lso[i]] = pal[i];
                *(uint4*)&sBh[lso[i]] = pbh[i];
                *(uint4*)&sBl[lso[i]] = pbl[i];
            }
            __syncthreads();
        }
    }

    if (mode == 2) {
        const int batch = row0 >> 10;
#pragma unroll
        for (int nt = 0; nt < 4; nt++)
#pragma unroll
            for (int j = 0; j < 2; j++) {
                float v = -CUDART_INF_F;
#pragma unroll
                for (int mt = 0; mt < 4; mt++)
                    v = fmaxf(v, fmaxf(acc[mt][nt][j], acc[mt][nt][j + 2]));
#pragma unroll
                for (int off = 4; off < 32; off <<= 1)
                    v = fmaxf(v, __shfl_xor_sync(0xffffffffu, v, off));
                if (lane < 4) {
                    int col = col0 + wc * 32 + nt * 8 + 2 * lane + j;
                    atomicMax(&gmax[batch * 1024 + col], encf(v));
                }
            }
        return;
    }

#pragma unroll
    for (int mt = 0; mt < 4; mt++)
#pragma unroll
        for (int nt = 0; nt < 4; nt++) {
            int r = row0 + wr * 64 + mt * 16 + g;
            int c = col0 + wc * 32 + nt * 8 + 2 * t;
            float v0 = acc[mt][nt][0], v1 = acc[mt][nt][1];
            float v2 = acc[mt][nt][2], v3 = acc[mt][nt][3];
            if (mode == 1) {
                float sr0 = sqb[r & 1023], sr8 = sqb[(r + 8) & 1023];
                float sc0 = sqb[c & 1023], sc1 = sqb[(c + 1) & 1023];
                v0 = 2.f * v0 - sr0 - sc0; v1 = 2.f * v1 - sr0 - sc1;
                v2 = 2.f * v2 - sr8 - sc0; v3 = 2.f * v3 - sr8 - sc1;
            }
            *(float2*)&C[(size_t)r * ldc + c] = make_float2(v0, v1);
            *(float2*)&C[(size_t)(r + 8) * ldc + c] = make_float2(v2, v3);
            if (mode == 1 && bi != bj) {
                C[(size_t)c * ldc + r] = v0;
                C[(size_t)(c + 1) * ldc + r] = v1;
                C[(size_t)c * ldc + r + 8] = v2;
                C[(size_t)(c + 1) * ldc + r + 8] = v3;
            }
        }
}

// ---------------- 128x128x8 FFMA SGEMM (layer 0 pq only, K=3) --------------
__global__ void __launch_bounds__(256, 2)
sgemm128(const float* __restrict__ A, int lda, long long sA,
         const float* __restrict__ B, int ldb, long long sB,
         const float* __restrict__ sq,
         float* __restrict__ C, int ldc, long long sC,
         int M, int N, int K, int mode)
{
    int bz = blockIdx.z;
    A += (long long)bz * sA;
    B += (long long)bz * sB;
    C += (long long)bz * sC;
    const float* sqb = sq ? (sq + (long long)bz * M) : nullptr;

    int bi, bj;
    if (mode == 1) {
        int nb = N >> 7;
        int p = blockIdx.x;
        bi = 0;
        while (p >= nb - bi) { p -= nb - bi; bi++; }
        bj = bi + p;
    } else { bi = blockIdx.x; bj = blockIdx.y; }
    const int row0 = bi * 128;
    const int col0 = bj * 128;

    __shared__ float As[2][8][132];
    __shared__ float Bs[2][8][132];

    const int tid = threadIdx.x;
    const int lk = tid & 7;
    const int lm = tid >> 3;
    const int tx = tid & 15;
    const int ty = tid >> 4;

    float acc[8][8];
#pragma unroll
    for (int i = 0; i < 8; i++)
#pragma unroll
        for (int j = 0; j < 8; j++) acc[i][j] = 0.f;

    float pa[4], pb[4];
    const int nk = (K + 7) >> 3;

    {
        int k = lk;
        bool ok = (k < K);
#pragma unroll
        for (int j = 0; j < 4; j++) {
            int m = lm + 32 * j;
            pa[j] = ok ? A[(long long)(row0 + m) * lda + k] : 0.f;
            pb[j] = ok ? B[(long long)(col0 + m) * ldb + k] : 0.f;
        }
#pragma unroll
        for (int j = 0; j < 4; j++) {
            As[0][lk][lm + 32 * j] = pa[j];
            Bs[0][lk][lm + 32 * j] = pb[j];
        }
    }
    __syncthreads();

    for (int t = 0; t < nk; t++) {
        int cur = t & 1;
        if (t + 1 < nk) {
            int k = (t + 1) * 8 + lk;
            bool ok = (k < K);
#pragma unroll
            for (int j = 0; j < 4; j++) {
                int m = lm + 32 * j;
                pa[j] = ok ? A[(long long)(row0 + m) * lda + k] : 0.f;
                pb[j] = ok ? B[(long long)(col0 + m) * ldb + k] : 0.f;
            }
        }
#pragma unroll
        for (int kk = 0; kk < 8; kk++) {
            float a[8], b[8];
            *(float4*)&a[0] = *(const float4*)&As[cur][kk][ty * 4];
            *(float4*)&a[4] = *(const float4*)&As[cur][kk][64 + ty * 4];
            *(float4*)&b[0] = *(const float4*)&Bs[cur][kk][tx * 4];
            *(float4*)&b[4] = *(const float4*)&Bs[cur][kk][64 + tx * 4];
#pragma unroll
            for (int i = 0; i < 8; i++)
#pragma unroll
                for (int j = 0; j < 8; j++)
                    acc[i][j] += a[i] * b[j];
        }
        if (t + 1 < nk) {
            int nxt = cur ^ 1;
#pragma unroll
            for (int j = 0; j < 4; j++) {
                As[nxt][lk][lm + 32 * j] = pa[j];
                Bs[nxt][lk][lm + 32 * j] = pb[j];
            }
        }
        __syncthreads();
    }

#pragma unroll
    for (int ih = 0; ih < 2; ih++) {
#pragma unroll
        for (int i = 0; i < 4; i++) {
            int r = row0 + ih * 64 + ty * 4 + i;
            float srow = (mode == 1) ? sqb[r] : 0.f;
#pragma unroll
            for (int jh = 0; jh < 2; jh++) {
                float outv[4];
#pragma unroll
                for (int j = 0; j < 4; j++) {
                    float v = acc[ih * 4 + i][jh * 4 + j];
                    if (mode == 1)
                        v = (2.f * v - srow) - sqb[col0 + jh * 64 + tx * 4 + j];
                    outv[j] = v;
                }
                *(float4*)&C[(long long)r * ldc + col0 + jh * 64 + tx * 4] =
                    *(float4*)&outv[0];
            }
        }
    }

    if (mode == 1 && bi != bj) {
#pragma unroll
        for (int jh = 0; jh < 2; jh++)
#pragma unroll
            for (int j = 0; j < 4; j++) {
                int c = col0 + jh * 64 + tx * 4 + j;
                float sc = sqb[c];
#pragma unroll
                for (int ih = 0; ih < 2; ih++) {
                    int rb = row0 + ih * 64 + ty * 4;
                    float mv[4];
#pragma unroll
                    for (int i = 0; i < 4; i++)
                        mv[i] = (2.f * acc[ih * 4 + i][jh * 4 + j] - sqb[rb + i]) - sc;
                    *(float4*)&C[(long long)c * ldc + rb] = *(float4*)&mv[0];
                }
            }
    }
}

// ---------------- squared norms (layer 0 input x only) -----------------------
__global__ void sq_kernel(const float* __restrict__ H, int lda, int C,
                          float* __restrict__ SQ)
{
    int gwarp = (blockIdx.x * blockDim.x + threadIdx.x) >> 5;
    int lane = threadIdx.x & 31;
    if (gwarp >= 16 * 1024) return;
    const float* h = H + (long long)gwarp * lda;
    float s = 0.f;
    for (int c = lane; c < C; c += 32) { float v = h[c]; s += v * v; }
#pragma unroll
    for (int d = 16; d > 0; d >>= 1) s += __shfl_down_sync(0xffffffffu, s, d);
    if (lane == 0) SQ[gwarp] = s;
}

// ---------------- shared top-40 radix-select body ----------------------------
// map_mode 0: m = tid*4 + j (dist-array kernel).  1: m = tid + 256*j (l0 fused).
struct TopkWs {
    unsigned hist[256];
    unsigned cntge[256];
    unsigned wsum[8];
    int shB;
    unsigned shGT;
    int outcnt, tiecnt;
    unsigned long long tlist[1024];
};

static __device__ __forceinline__ int kmap(int tid, int j, int map_mode) {
    return map_mode ? (tid + 256 * j) : (tid * 4 + j);
}

static __device__ void topk_select(unsigned key[4], TopkWs* ws,
                                   int row, int* __restrict__ IDX, int map_mode)
{
    int tid = threadIdx.x;
    int lane = tid & 31, w = tid >> 5;
    bool cand[4] = {true, true, true, true};

    unsigned prefix = 0;
    int kneed = 40;
    unsigned lo = 0, hi = 0;
    int kn = 0;
    int fin = 0;

    for (int level = 0; level < 4 && !fin; level++) {
        const int shift = 24 - 8 * level;
        ws->hist[tid] = 0;
        __syncthreads();
#pragma unroll
        for (int j = 0; j < 4; j++)
            if (cand[j]) atomicAdd(&ws->hist[(key[j] >> shift) & 255u], 1u);
        __syncthreads();

        unsigned v = ws->hist[255 - tid];
#pragma unroll
        for (int d = 1; d < 32; d <<= 1) {
            unsigned n = __shfl_up_sync(0xffffffffu, v, d);
            if (lane >= d) v += n;
        }
        if (lane == 31) ws->wsum[w] = v;
        __syncthreads();
        if (tid == 0) {
            unsigned a = 0;
#pragma unroll
            for (int q = 0; q < 8; q++) { unsigned t2 = ws->wsum[q]; ws->wsum[q] = a; a += t2; }
        }
        __syncthreads();
        ws->cntge[255 - tid] = v + ws->wsum[w];
        __syncthreads();

        unsigned geb = ws->cntge[tid];
        unsigned geb1 = (tid == 255) ? 0u : ws->cntge[tid + 1];
        if (geb >= (unsigned)kneed && geb1 < (unsigned)kneed) {
            ws->shB = tid;
            ws->shGT = geb1;
        }
        __syncthreads();
        int B = ws->shB;
        int gt = (int)ws->shGT;
        kn = kneed - gt;
        int hb = (int)ws->hist[B];
        lo = prefix | ((unsigned)B << shift);
        hi = lo + ((shift < 32) ? ((1u << shift) - 1u) : 0u);
        if (hb == kn) {
            fin = 1;
        } else if (hb <= 96 || shift == 0) {
            fin = 2;
        } else {
            prefix = lo;
            kneed = kn;
#pragma unroll
            for (int j = 0; j < 4; j++)
                cand[j] = cand[j] && (((key[j] >> shift) & 255u) == (unsigned)B);
        }
        __syncthreads();
    }

    if (tid == 0) { ws->outcnt = 0; ws->tiecnt = 0; }
    __syncthreads();

    if (fin == 1) {
        unsigned T = lo - 1u;
#pragma unroll
        for (int j = 0; j < 4; j++) {
            if (key[j] > T) {
                int slot = atomicAdd(&ws->outcnt, 1);
                IDX[row * 40 + slot] = kmap(tid, j, map_mode);
            }
        }
        return;
    }

#pragma unroll
    for (int j = 0; j < 4; j++) {
        int m = kmap(tid, j, map_mode);
        unsigned k2 = key[j];
        if (k2 > hi) {
            int slot = atomicAdd(&ws->outcnt, 1);
            IDX[row * 40 + slot] = m;
        } else if (k2 >= lo) {
            int t2 = atomicAdd(&ws->tiecnt, 1);
            ws->tlist[t2] = ((unsigned long long)k2 << 32) | (unsigned)(2047 - m);
        }
    }
    __syncthreads();

    int tt = ws->tiecnt;
    for (int p = tid; p < tt; p += 256) {
        unsigned long long me = ws->tlist[p];
        int rk = 0;
        for (int q = 0; q < tt; q++) rk += (ws->tlist[q] > me);
        if (rk < kn) {
            int slot = atomicAdd(&ws->outcnt, 1);
            IDX[row * 40 + slot] = 2047 - (int)(me & 0xFFFFFFFFull);
        }
    }
}

// ---------------- top-40 from dist array (layers 1-3) ------------------------
__global__ void __launch_bounds__(256)
topk40_kernel(const float* __restrict__ S, int* __restrict__ IDX)
{
    __shared__ TopkWs ws;
    int row = blockIdx.x;
    const float* s = S + (long long)row * 1024;
    int tid = threadIdx.x;

    unsigned key[4];
    {
        float4 v = ((const float4*)s)[tid];
        key[0] = encf(v.x); key[1] = encf(v.y);
        key[2] = encf(v.z); key[3] = encf(v.w);
    }
    topk_select(key, &ws, row, IDX, 0);
}

// ---------------- layer-0 fused distance + top-40 ----------------------------
// Computes dist bit-identically to the old sgemm path:
// acc = fma chain over 3 coords; v = (2*acc - sq_r) - sq_m.
__global__ void __launch_bounds__(256)
topk40_l0(const float* __restrict__ X, const float* __restrict__ SQ,
          int* __restrict__ IDX)
{
    __shared__ TopkWs ws;
    __shared__ float sx[1024], sy[1024], sz[1024], ss[1024];

    int row = blockIdx.x;
    int b = row >> 10, r = row & 1023;
    int tid = threadIdx.x;

    const float* xb = X + (size_t)b * 1024 * 3;
#pragma unroll
    for (int it = 0; it < 3; it++) {
        int j = it * 256 + tid;               // 768 float4 groups
        float4 v = ((const float4*)xb)[j];
        float vv[4] = {v.x, v.y, v.z, v.w};
#pragma unroll
        for (int e = 0; e < 4; e++) {
            int idx = 4 * j + e;
            int p = idx / 3, c = idx - 3 * p;
            float* dstp = (c == 0) ? sx : ((c == 1) ? sy : sz);
            dstp[p] = vv[e];
        }
    }
    for (int j = tid; j < 1024; j += 256) ss[j] = SQ[b * 1024 + j];
    __syncthreads();

    float xr = sx[r], yr = sy[r], zr = sz[r], sr = ss[r];
    unsigned key[4];
#pragma unroll
    for (int j = 0; j < 4; j++) {
        int m = tid + 256 * j;                // stride-1 smem access
        float acc = 0.f;
        acc = fmaf(xr, sx[m], acc);
        acc = fmaf(yr, sy[m], acc);
        acc = fmaf(zr, sz[m], acc);
        float v = (2.f * acc - sr) - ss[m];
        key[j] = encf(v);
    }
    topk_select(key, &ws, row, IDX, 1);
}

// ---------------- weight transform (all 4 layers, one launch) ---------------
__global__ void wprep_all(const float* __restrict__ W0, const float* __restrict__ W1,
                          const float* __restrict__ W2, const float* __restrict__ W3,
                          float* __restrict__ WPQ)
{
    int i = blockIdx.x * blockDim.x + threadIdx.x;
    // layers: sizes CoxC = 64x3, 64x64, 128x64, 256x128; offsets in WPQ.
    const int n0 = 64 * 3, n1 = 64 * 64, n2 = 128 * 64, n3 = 256 * 128;
    const float* W; int Co, C, off;
    if (i < n0)                { W = W0; Co = 64;  C = 3;   off = 0;     }
    else if ((i -= n0) < n1)   { W = W1; Co = 64;  C = 64;  off = 1024;  }
    else if ((i -= n1) < n2)   { W = W2; Co = 128; C = 64;  off = 9216;  }
    else if ((i -= n2) < n3)   { W = W3; Co = 256; C = 128; off = 25600; }
    else return;
    int o = i / C, c = i % C;
    float wl = W[o * 2 * C + c];
    float wr = W[o * 2 * C + C + c];
    WPQ[off + o * C + c] = wl;
    WPQ[off + (Co + o) * C + c] = wr - wl;
}

// ---------------- gather-max + fused sq + fp16-split outputs ----------------
__global__ void __launch_bounds__(128)
edge_gathermax(const float* __restrict__ PQ,
               const int* __restrict__ IDX,
               const float* __restrict__ g,
               const float* __restrict__ bb,
               uint32_t* __restrict__ AH, uint32_t* __restrict__ AL,
               uint32_t* __restrict__ CH, uint32_t* __restrict__ CL,
               float* __restrict__ SQ,
               int Co, int cwoff, int write_sq, int write_a)
{
    const float BN_INV = 0.9999950000374997f;
    const int c4n = Co >> 2;
    const int G = 128 / c4n;
    const int pbase = blockIdx.x * G;

    __shared__ int nb[8 * 40];
    for (int i = threadIdx.x; i < G * 40; i += 128)
        nb[i] = IDX[(pbase + i / 40) * 40 + (i % 40)];
    __syncthreads();

    const int p = threadIdx.x / c4n;
    const int o = (threadIdx.x - p * c4n) * 4;
    const int pt = pbase + p;
    const int b = pt >> 10;
    const int ld = 2 * Co;
    const float* base = PQ + (size_t)(b << 10) * ld + o;
    const int* nbp = nb + p * 40;

    float4 mx = make_float4(-CUDART_INF_F, -CUDART_INF_F, -CUDART_INF_F, -CUDART_INF_F);
    float4 mn = make_float4(CUDART_INF_F, CUDART_INF_F, CUDART_INF_F, CUDART_INF_F);
#pragma unroll 8
    for (int k = 0; k < 40; k++) {
        float4 v = *(const float4*)(base + (size_t)nbp[k] * ld);
        mx.x = fmaxf(mx.x, v.x); mn.x = fminf(mn.x, v.x);
        mx.y = fmaxf(mx.y, v.y); mn.y = fminf(mn.y, v.y);
        mx.z = fmaxf(mx.z, v.z); mn.z = fminf(mn.z, v.z);
        mx.w = fmaxf(mx.w, v.w); mn.w = fminf(mn.w, v.w);
    }
    float4 q  = *(const float4*)&PQ[(size_t)pt * ld + Co + o];
    float4 gg = *(const float4*)&g[o];
    float4 bv = *(const float4*)&bb[o];

    float4 y;
    y.x = (gg.x >= 0.f ? mx.x : mn.x) + q.x;
    y.y = (gg.y >= 0.f ? mx.y : mn.y) + q.y;
    y.z = (gg.z >= 0.f ? mx.z : mn.z) + q.z;
    y.w = (gg.w >= 0.f ? mx.w : mn.w) + q.w;
    y.x = gg.x * (y.x * BN_INV) + bv.x;
    y.y = gg.y * (y.y * BN_INV) + bv.y;
    y.z = gg.z * (y.z * BN_INV) + bv.z;
    y.w = gg.w * (y.w * BN_INV) + bv.w;
    y.x = y.x > 0.f ? y.x : 0.2f * y.x;
    y.y = y.y > 0.f ? y.y : 0.2f * y.y;
    y.z = y.z > 0.f ? y.z : 0.2f * y.z;
    y.w = y.w > 0.f ? y.w : 0.2f * y.w;

    uint2 h, l;
    hsplit2(y.x, y.y, h.x, l.x);
    hsplit2(y.z, y.w, h.y, l.y);
    const int ow = o >> 1;
    const int Cw = Co >> 1;
    if (write_a) {
        *(uint2*)&AH[(size_t)pt * Cw + ow] = h;
        *(uint2*)&AL[(size_t)pt * Cw + ow] = l;
    }
    *(uint2*)&CH[(size_t)pt * 256 + cwoff + ow] = h;
    *(uint2*)&CL[(size_t)pt * 256 + cwoff + ow] = l;

    if (write_sq) {
        float s = y.x * y.x + y.y * y.y + y.z * y.z + y.w * y.w;
        for (int off = c4n >> 1; off >= 1; off >>= 1)
            s += __shfl_xor_sync(0xffffffffu, s, off);
        if ((threadIdx.x & (c4n - 1)) == 0) SQ[pt] = s;
    }
}

// ---------------- gmax init / decode ----------------------------------------
__global__ void gmax_init(unsigned* __restrict__ g)
{
    g[blockIdx.x * 1024 + threadIdx.x] = 0u;
}

__global__ void decode_out(const unsigned* __restrict__ g,
                           const float* __restrict__ bf, float* __restrict__ out)
{
    int i = blockIdx.x * 256 + threadIdx.x;
    unsigned e = g[i];
    unsigned u = (e & 0x80000000u) ? (e ^ 0x80000000u) : ~e;
    out[i] = __uint_as_float(u) + bf[i & 1023];
}

// ---------------- launch -----------------------------------------------------
extern "C" void kernel_launch(void* const* d_in, const int* in_sizes, int n_in,
                              void* d_out, int out_size)
{
    (void)in_sizes; (void)n_in; (void)out_size;
    const float* x  = (const float*)d_in[0];
    const float* w[4]  = {(const float*)d_in[1], (const float*)d_in[4],
                          (const float*)d_in[7], (const float*)d_in[10]};
    const float* g[4]  = {(const float*)d_in[2], (const float*)d_in[5],
                          (const float*)d_in[8], (const float*)d_in[11]};
    const float* bb[4] = {(const float*)d_in[3], (const float*)d_in[6],
                          (const float*)d_in[9], (const float*)d_in[12]};
    const float* wf = (const float*)d_in[13];
    const float* bf = (const float*)d_in[14];
    float* out = (float*)d_out;

    float *dist, *sq, *pq, *wpq; int* idx; unsigned* gm;
    uint32_t *ah, *al, *wh, *wl, *fh, *fl, *chp, *clp;
    cudaGetSymbolAddress((void**)&dist, d_dist);
    cudaGetSymbolAddress((void**)&sq,   d_sq);
    cudaGetSymbolAddress((void**)&idx,  d_idx);
    cudaGetSymbolAddress((void**)&pq,   d_pq);
    cudaGetSymbolAddress((void**)&wpq,  d_wpq);
    cudaGetSymbolAddress((void**)&gm,   d_gmax);
    cudaGetSymbolAddress((void**)&ah,   d_ah);
    cudaGetSymbolAddress((void**)&al,   d_al);
    cudaGetSymbolAddress((void**)&wh,   d_wh);
    cudaGetSymbolAddress((void**)&wl,   d_wl);
    cudaGetSymbolAddress((void**)&fh,   d_fh);
    cudaGetSymbolAddress((void**)&fl,   d_fl);
    cudaGetSymbolAddress((void**)&chp,  d_ch);
    cudaGetSymbolAddress((void**)&clp,  d_cl);

    cudaFuncSetAttribute(hgemm, cudaFuncAttributeMaxDynamicSharedMemorySize,
                         HSMEM);

    const int woffw[4] = {0, 512, 4608, 12800};
    const int offs[4]  = {0, 64, 128, 256};
    const int Cs[4]    = {3, 64, 64, 128};
    const int Cos[4]   = {64, 64, 128, 256};

    // launch order: #4 = topk40_l0 (profiled slot)
    wprep_all<<<(45248 + 255) / 256, 256>>>(w[0], w[1], w[2], w[3], wpq);
    gmax_init<<<16, 1024>>>(gm);
    sq_kernel<<<2048, 256>>>(x, 3, 3, sq);
    topk40_l0<<<16384, 256>>>(x, sq, idx);                 // fused dist+topk, l0
    cvt1d_h<<<(92160 / 4 + 255) / 256, 256>>>(wpq, wh, wl, 92160 / 4);
    cvt1d_h<<<(1024 * 512 / 4 + 255) / 256, 256>>>(wf, fh, fl, 1024 * 512 / 4);
    sgemm128<<<dim3(128, 1, 1), 256>>>(
        x, 3, 0, wpq, 3, 0, nullptr,
        pq, 128, 0, 16384, 128, 3, 0);
    edge_gathermax<<<2048, 128>>>(pq, idx, g[0], bb[0],
                                  ah, al, chp, clp, sq,
                                  64, offs[0] / 2, 1, 1);

    // layers 1-3 on tensor cores (fp16x3)
    for (int l = 1; l < 4; l++) {
        int C = Cs[l], Co = Cos[l];
        int Cw = C >> 1;

        hgemm<<<dim3(36, 1, 16), 256, HSMEM>>>(
            ah, al, Cw, 1024LL * Cw, nullptr, nullptr, 0, sq,
            dist, 1024, 1024LL * 1024, 1024, C, 1, nullptr);
        topk40_kernel<<<16384, 256>>>(dist, idx);
        hgemm<<<dim3(128, (2 * Co) / 128, 1), 256, HSMEM>>>(
            ah, al, Cw, 0, wh + woffw[l], wl + woffw[l], Cw, nullptr,
            pq, 2 * Co, 0, 2 * Co, C, 0, nullptr);
        edge_gathermax<<<16384 * Co / 512, 128>>>(pq, idx, g[l], bb[l],
                                                  ah, al, chp, clp, sq,
                                                  Co, offs[l] / 2,
                                                  (l < 3) ? 1 : 0,
                                                  (l < 3) ? 1 : 0);
    }

    // final linear 512 -> 1024 (fp16x3, fused max over N)
    hgemm<<<dim3(128, 8, 1), 256, HSMEM>>>(
        chp, clp, 256, 0, fh, fl, 256, nullptr,
        dist, 0, 0, 1024, 512, 2, gm);
    decode_out<<<64, 256>>>(gm, bf, out);
}

// round 16
// speedup vs baseline: 1.0393x; 1.0393x over previous
#include <cuda_runtime.h>
#include <cuda_fp16.h>
#include <math_constants.h>
#include <cstdint>

// ---------------- scratch (static device globals; no allocation) ------------
__device__ float    d_dist[16 * 1024 * 1024];
__device__ float    d_sq  [16 * 1024];
__device__ int      d_idx [16 * 1024 * 40];
__device__ float    d_pq  [16 * 1024 * 512];
__device__ float    d_wpq [92160];
__device__ unsigned d_gmax[16 * 1024];
// fp16-split planes (packed half2 words, k-pairs)
__device__ uint32_t d_ah[16 * 1024 * 64], d_al[16 * 1024 * 64];   // layer input (C<=128)
__device__ uint32_t d_wh[46080],          d_wl[46080];            // wpq
__device__ uint32_t d_fh[1024 * 256],     d_fl[1024 * 256];       // wf
__device__ uint32_t d_ch[16 * 1024 * 256], d_cl[16 * 1024 * 256]; // full cat

static __device__ __forceinline__ unsigned encf(float v) {
    unsigned u = __float_as_uint(v);
    return (u & 0x80000000u) ? ~u : (u | 0x80000000u);
}
static __device__ __forceinline__ void hsplit2(float a, float b,
                                               uint32_t& h, uint32_t& l) {
    __half ha = __float2half_rn(a), hb = __float2half_rn(b);
    __half la = __float2half_rn(a - __half2float(ha));
    __half lb = __float2half_rn(b - __half2float(hb));
    __half2 H = __halves2half2(ha, hb), L = __halves2half2(la, lb);
    h = *(uint32_t*)&H;
    l = *(uint32_t*)&L;
}
static __device__ __forceinline__ void mma_f16(float* c, uint32_t a0, uint32_t a1,
                                               uint32_t a2, uint32_t a3,
                                               uint32_t b0, uint32_t b1) {
    asm volatile(
        "mma.sync.aligned.m16n8k16.row.col.f32.f16.f16.f32 "
        "{%0,%1,%2,%3}, {%4,%5,%6,%7}, {%8,%9}, {%0,%1,%2,%3};"
        : "+f"(c[0]), "+f"(c[1]), "+f"(c[2]), "+f"(c[3])
        : "r"(a0), "r"(a1), "r"(a2), "r"(a3), "r"(b0), "r"(b1));
}

static constexpr int KSW   = 128 * 12;
static constexpr int PLW   = 2 * KSW;
static constexpr int HSMEM = 4 * PLW * 4;   // 49152 bytes

// ---------------- weight conversion ------------------------------------------
__global__ void cvt1d_h(const float* __restrict__ src, uint32_t* __restrict__ hi,
                        uint32_t* __restrict__ lo, int n4)
{
    int i = blockIdx.x * 256 + threadIdx.x;
    if (i >= n4) return;
    float4 v = ((const float4*)src)[i];
    uint2 h, l;
    hsplit2(v.x, v.y, h.x, l.x);
    hsplit2(v.z, v.w, h.y, l.y);
    ((uint2*)hi)[i] = h;
    ((uint2*)lo)[i] = l;
}

// ============ fp16x3 tensor GEMM: C = A(..xK) * B(NxK)^T ====================
__global__ void __launch_bounds__(256, 2)
hgemm(const uint32_t* __restrict__ Ah, const uint32_t* __restrict__ Al,
      int ldaw, long long sA,
      const uint32_t* __restrict__ Bh, const uint32_t* __restrict__ Bl,
      int ldbw,
      const float* __restrict__ sq,
      float* __restrict__ C, int ldc, long long sC,
      int N, int K, int mode, unsigned* __restrict__ gmax)
{
    extern __shared__ uint32_t dsm[];
    uint32_t* sAh = dsm;
    uint32_t* sAl = sAh + PLW;
    uint32_t* sBh = sAl + PLW;
    uint32_t* sBl = sBh + PLW;

    int bz = blockIdx.z;
    Ah += (long long)bz * sA;
    Al += (long long)bz * sA;
    const float* sqb = sq ? sq + (long long)bz * 1024 : nullptr;
    C += (long long)bz * sC;

    int bi, bj;
    if (mode == 1) {
        int nb = N >> 7;
        int p = blockIdx.x;
        bi = 0;
        while (p >= nb - bi) { p -= nb - bi; bi++; }
        bj = bi + p;
    } else { bi = blockIdx.x; bj = blockIdx.y; }
    const int row0 = bi * 128, col0 = bj * 128;

    const uint32_t* Bh2 = (mode == 1) ? Ah : Bh;
    const uint32_t* Bl2 = (mode == 1) ? Al : Bl;
    const int ldb2 = (mode == 1) ? ldaw : ldbw;

    const int tid = threadIdx.x;
    const int wid = tid >> 5, lane = tid & 31;
    const int wr = wid >> 2, wc = wid & 3;
    const int g = lane >> 2, t = lane & 3;

    float acc[4][4][4];
#pragma unroll
    for (int mt = 0; mt < 4; mt++)
#pragma unroll
        for (int nt = 0; nt < 4; nt++)
#pragma unroll
            for (int i = 0; i < 4; i++) acc[mt][nt][i] = 0.f;

    int lrow[2], lw4[2], lso[2];
    size_t loa[2], lob[2];
#pragma unroll
    for (int i = 0; i < 2; i++) {
        int id4 = i * 256 + tid;
        lrow[i] = id4 >> 2;
        lw4[i] = id4 & 3;
        int ks = lw4[i] >> 1, wi = (lw4[i] & 1) * 4;
        lso[i] = ks * KSW + lrow[i] * 12 + wi;
        loa[i] = (size_t)(row0 + lrow[i]) * ldaw + lw4[i] * 4;
        lob[i] = (size_t)(col0 + lrow[i]) * ldb2 + lw4[i] * 4;
    }

    uint4 pah[2], pal[2], pbh[2], pbl[2];
    const int nch = K >> 5;

#pragma unroll
    for (int i = 0; i < 2; i++) {
        pah[i] = *(const uint4*)&Ah[loa[i]];
        pal[i] = *(const uint4*)&Al[loa[i]];
        pbh[i] = *(const uint4*)&Bh2[lob[i]];
        pbl[i] = *(const uint4*)&Bl2[lob[i]];
    }
#pragma unroll
    for (int i = 0; i < 2; i++) {
        *(uint4*)&sAh[lso[i]] = pah[i];
        *(uint4*)&sAl[lso[i]] = pal[i];
        *(uint4*)&sBh[lso[i]] = pbh[i];
        *(uint4*)&sBl[lso[i]] = pbl[i];
    }
    __syncthreads();

    for (int ch = 0; ch < nch; ch++) {
        if (ch + 1 < nch) {
            const int k1 = (ch + 1) * 16;
#pragma unroll
            for (int i = 0; i < 2; i++) {
                pah[i] = *(const uint4*)&Ah[loa[i] + k1];
                pal[i] = *(const uint4*)&Al[loa[i] + k1];
                pbh[i] = *(const uint4*)&Bh2[lob[i] + k1];
                pbl[i] = *(const uint4*)&Bl2[lob[i] + k1];
            }
        }

#pragma unroll
        for (int ks = 0; ks < 2; ks++) {
            const uint32_t* pAh = sAh + ks * KSW;
            const uint32_t* pAl = sAl + ks * KSW;
            const uint32_t* pBh = sBh + ks * KSW;
            const uint32_t* pBl = sBl + ks * KSW;

            uint32_t bh0[4], bh1[4], bl0[4], bl1[4];
#pragma unroll
            for (int nt = 0; nt < 4; nt++) {
                int nb_ = wc * 32 + nt * 8 + g;
                bh0[nt] = pBh[nb_ * 12 + t];
                bh1[nt] = pBh[nb_ * 12 + 4 + t];
                bl0[nt] = pBl[nb_ * 12 + t];
                bl1[nt] = pBl[nb_ * 12 + 4 + t];
            }
            uint32_t a[4][4];
#pragma unroll
            for (int mt = 0; mt < 4; mt++) {
                int rb = wr * 64 + mt * 16 + g;
                a[mt][0] = pAh[rb * 12 + t];
                a[mt][1] = pAh[(rb + 8) * 12 + t];
                a[mt][2] = pAh[rb * 12 + 4 + t];
                a[mt][3] = pAh[(rb + 8) * 12 + 4 + t];
            }
#pragma unroll
            for (int nt = 0; nt < 4; nt++)
#pragma unroll
                for (int mt = 0; mt < 4; mt++) {
                    mma_f16(acc[mt][nt], a[mt][0], a[mt][1], a[mt][2], a[mt][3],
                            bh0[nt], bh1[nt]);
                    mma_f16(acc[mt][nt], a[mt][0], a[mt][1], a[mt][2], a[mt][3],
                            bl0[nt], bl1[nt]);
                }
#pragma unroll
            for (int mt = 0; mt < 4; mt++) {
                int rb = wr * 64 + mt * 16 + g;
                a[mt][0] = pAl[rb * 12 + t];
                a[mt][1] = pAl[(rb + 8) * 12 + t];
                a[mt][2] = pAl[rb * 12 + 4 + t];
                a[mt][3] = pAl[(rb + 8) * 12 + 4 + t];
            }
#pragma unroll
            for (int nt = 0; nt < 4; nt++)
#pragma unroll
                for (int mt = 0; mt < 4; mt++)
                    mma_f16(acc[mt][nt], a[mt][0], a[mt][1], a[mt][2], a[mt][3],
                            bh0[nt], bh1[nt]);
        }
        __syncthreads();
        if (ch + 1 < nch) {
#pragma unroll
            for (int i = 0; i < 2; i++) {
                *(uint4*)&sAh[lso[i]] = pah[i];
                *(uint4*)&sAl[lso[i]] = pal[i];
                *(uint4*)&sBh[lso[i]] = pbh[i];
                *(uint4*)&sBl[lso[i]] = pbl[i];
            }
            __syncthreads();
        }
    }

    if (mode == 2) {
        const int batch = row0 >> 10;
#pragma unroll
        for (int nt = 0; nt < 4; nt++)
#pragma unroll
            for (int j = 0; j < 2; j++) {
                float v = -CUDART_INF_F;
#pragma unroll
                for (int mt = 0; mt < 4; mt++)
                    v = fmaxf(v, fmaxf(acc[mt][nt][j], acc[mt][nt][j + 2]));
#pragma unroll
                for (int off = 4; off < 32; off <<= 1)
                    v = fmaxf(v, __shfl_xor_sync(0xffffffffu, v, off));
                if (lane < 4) {
                    int col = col0 + wc * 32 + nt * 8 + 2 * lane + j;
                    atomicMax(&gmax[batch * 1024 + col], encf(v));
                }
            }
        return;
    }

#pragma unroll
    for (int mt = 0; mt < 4; mt++)
#pragma unroll
        for (int nt = 0; nt < 4; nt++) {
            int r = row0 + wr * 64 + mt * 16 + g;
            int c = col0 + wc * 32 + nt * 8 + 2 * t;
            float v0 = acc[mt][nt][0], v1 = acc[mt][nt][1];
            float v2 = acc[mt][nt][2], v3 = acc[mt][nt][3];
            if (mode == 1) {
                float sr0 = sqb[r & 1023], sr8 = sqb[(r + 8) & 1023];
                float sc0 = sqb[c & 1023], sc1 = sqb[(c + 1) & 1023];
                v0 = 2.f * v0 - sr0 - sc0; v1 = 2.f * v1 - sr0 - sc1;
                v2 = 2.f * v2 - sr8 - sc0; v3 = 2.f * v3 - sr8 - sc1;
            }
            *(float2*)&C[(size_t)r * ldc + c] = make_float2(v0, v1);
            *(float2*)&C[(size_t)(r + 8) * ldc + c] = make_float2(v2, v3);
            if (mode == 1 && bi != bj) {
                C[(size_t)c * ldc + r] = v0;
                C[(size_t)(c + 1) * ldc + r] = v1;
                C[(size_t)c * ldc + r + 8] = v2;
                C[(size_t)(c + 1) * ldc + r + 8] = v3;
            }
        }
}

// ---------------- 128x128x8 FFMA SGEMM (layer 0 pq only, K=3) --------------
__global__ void __launch_bounds__(256, 2)
sgemm128(const float* __restrict__ A, int lda, long long sA,
         const float* __restrict__ B, int ldb, long long sB,
         const float* __restrict__ sq,
         float* __restrict__ C, int ldc, long long sC,
         int M, int N, int K, int mode)
{
    int bz = blockIdx.z;
    A += (long long)bz * sA;
    B += (long long)bz * sB;
    C += (long long)bz * sC;
    const float* sqb = sq ? (sq + (long long)bz * M) : nullptr;

    int bi, bj;
    if (mode == 1) {
        int nb = N >> 7;
        int p = blockIdx.x;
        bi = 0;
        while (p >= nb - bi) { p -= nb - bi; bi++; }
        bj = bi + p;
    } else { bi = blockIdx.x; bj = blockIdx.y; }
    const int row0 = bi * 128;
    const int col0 = bj * 128;

    __shared__ float As[2][8][132];
    __shared__ float Bs[2][8][132];

    const int tid = threadIdx.x;
    const int lk = tid & 7;
    const int lm = tid >> 3;
    const int tx = tid & 15;
    const int ty = tid >> 4;

    float acc[8][8];
#pragma unroll
    for (int i = 0; i < 8; i++)
#pragma unroll
        for (int j = 0; j < 8; j++) acc[i][j] = 0.f;

    float pa[4], pb[4];
    const int nk = (K + 7) >> 3;

    {
        int k = lk;
        bool ok = (k < K);
#pragma unroll
        for (int j = 0; j < 4; j++) {
            int m = lm + 32 * j;
            pa[j] = ok ? A[(long long)(row0 + m) * lda + k] : 0.f;
            pb[j] = ok ? B[(long long)(col0 + m) * ldb + k] : 0.f;
        }
#pragma unroll
        for (int j = 0; j < 4; j++) {
            As[0][lk][lm + 32 * j] = pa[j];
            Bs[0][lk][lm + 32 * j] = pb[j];
        }
    }
    __syncthreads();

    for (int t = 0; t < nk; t++) {
        int cur = t & 1;
        if (t + 1 < nk) {
            int k = (t + 1) * 8 + lk;
            bool ok = (k < K);
#pragma unroll
            for (int j = 0; j < 4; j++) {
                int m = lm + 32 * j;
                pa[j] = ok ? A[(long long)(row0 + m) * lda + k] : 0.f;
                pb[j] = ok ? B[(long long)(col0 + m) * ldb + k] : 0.f;
            }
        }
#pragma unroll
        for (int kk = 0; kk < 8; kk++) {
            float a[8], b[8];
            *(float4*)&a[0] = *(const float4*)&As[cur][kk][ty * 4];
            *(float4*)&a[4] = *(const float4*)&As[cur][kk][64 + ty * 4];
            *(float4*)&b[0] = *(const float4*)&Bs[cur][kk][tx * 4];
            *(float4*)&b[4] = *(const float4*)&Bs[cur][kk][64 + tx * 4];
#pragma unroll
            for (int i = 0; i < 8; i++)
#pragma unroll
                for (int j = 0; j < 8; j++)
                    acc[i][j] += a[i] * b[j];
        }
        if (t + 1 < nk) {
            int nxt = cur ^ 1;
#pragma unroll
            for (int j = 0; j < 4; j++) {
                As[nxt][lk][lm + 32 * j] = pa[j];
                Bs[nxt][lk][lm + 32 * j] = pb[j];
            }
        }
        __syncthreads();
    }

#pragma unroll
    for (int ih = 0; ih < 2; ih++) {
#pragma unroll
        for (int i = 0; i < 4; i++) {
            int r = row0 + ih * 64 + ty * 4 + i;
            float srow = (mode == 1) ? sqb[r] : 0.f;
#pragma unroll
            for (int jh = 0; jh < 2; jh++) {
                float outv[4];
#pragma unroll
                for (int j = 0; j < 4; j++) {
                    float v = acc[ih * 4 + i][jh * 4 + j];
                    if (mode == 1)
                        v = (2.f * v - srow) - sqb[col0 + jh * 64 + tx * 4 + j];
                    outv[j] = v;
                }
                *(float4*)&C[(long long)r * ldc + col0 + jh * 64 + tx * 4] =
                    *(float4*)&outv[0];
            }
        }
    }

    if (mode == 1 && bi != bj) {
#pragma unroll
        for (int jh = 0; jh < 2; jh++)
#pragma unroll
            for (int j = 0; j < 4; j++) {
                int c = col0 + jh * 64 + tx * 4 + j;
                float sc = sqb[c];
#pragma unroll
                for (int ih = 0; ih < 2; ih++) {
                    int rb = row0 + ih * 64 + ty * 4;
                    float mv[4];
#pragma unroll
                    for (int i = 0; i < 4; i++)
                        mv[i] = (2.f * acc[ih * 4 + i][jh * 4 + j] - sqb[rb + i]) - sc;
                    *(float4*)&C[(long long)c * ldc + rb] = *(float4*)&mv[0];
                }
            }
    }
}

// ---------------- squared norms (layer 0 input x only) -----------------------
__global__ void sq_kernel(const float* __restrict__ H, int lda, int C,
                          float* __restrict__ SQ)
{
    int gwarp = (blockIdx.x * blockDim.x + threadIdx.x) >> 5;
    int lane = threadIdx.x & 31;
    if (gwarp >= 16 * 1024) return;
    const float* h = H + (long long)gwarp * lda;
    float s = 0.f;
    for (int c = lane; c < C; c += 32) { float v = h[c]; s += v * v; }
#pragma unroll
    for (int d = 16; d > 0; d >>= 1) s += __shfl_down_sync(0xffffffffu, s, d);
    if (lane == 0) SQ[gwarp] = s;
}

// ---------------- top-40: single-level 2048-bin radix + brute force ----------
// map_mode 0: m = tid*4 + j.  1: m = tid + 256*j.
struct TopkWs {
    unsigned hist[2048];
    unsigned cs[256];
    unsigned wsum[8];
    int shB;
    unsigned shGT;
    int outcnt, tiecnt;
    unsigned long long tlist[1024];
};

static __device__ __forceinline__ int kmap(int tid, int j, int map_mode) {
    return map_mode ? (tid + 256 * j) : (tid * 4 + j);
}

static __device__ void topk_select(unsigned key[4], TopkWs* ws,
                                   int row, int* __restrict__ IDX, int map_mode)
{
    int tid = threadIdx.x;
    int lane = tid & 31, w = tid >> 5;

    // zero hist + counters
#pragma unroll
    for (int j = 0; j < 8; j++) ws->hist[tid + 256 * j] = 0;
    if (tid == 0) { ws->outcnt = 0; ws->tiecnt = 0; }
    __syncthreads();

    // 11-bit histogram
#pragma unroll
    for (int j = 0; j < 4; j++)
        atomicAdd(&ws->hist[key[j] >> 21], 1u);
    __syncthreads();

    // local suffix over owned chunk [8*tid, 8*tid+8)
    uint4 h0 = *(const uint4*)&ws->hist[tid * 8];
    uint4 h1 = *(const uint4*)&ws->hist[tid * 8 + 4];
    unsigned hh[8] = {h0.x, h0.y, h0.z, h0.w, h1.x, h1.y, h1.z, h1.w};
    unsigned suf[8];
    unsigned tot = 0;
#pragma unroll
    for (int j = 7; j >= 0; j--) { tot += hh[j]; suf[j] = tot; }

    ws->cs[tid] = tot;
    __syncthreads();

    // inclusive suffix over 256 chunk totals
    unsigned v = ws->cs[255 - tid];
#pragma unroll
    for (int d = 1; d < 32; d <<= 1) {
        unsigned n = __shfl_up_sync(0xffffffffu, v, d);
        if (lane >= d) v += n;
    }
    if (lane == 31) ws->wsum[w] = v;
    __syncthreads();
    if (tid == 0) {
        unsigned a = 0;
#pragma unroll
        for (int q = 0; q < 8; q++) { unsigned t2 = ws->wsum[q]; ws->wsum[q] = a; a += t2; }
    }
    __syncthreads();
    unsigned inc = v + ws->wsum[w];      // suffix incl chunk (255 - tid)
    ws->cs[255 - tid] = inc;
    __syncthreads();

    // boundary bin B: F(B) >= 40 > F(B+1);  F(8t+j) = suf[j] + (cs[t] - tot)
    {
        unsigned ex = ws->cs[tid] - tot;
        unsigned Fn = ex;                // F of bin 8*tid+8
#pragma unroll
        for (int j = 7; j >= 0; j--) {
            unsigned Fb = suf[j] + ex;
            if (Fb >= 40u && Fn < 40u) { ws->shB = tid * 8 + j; ws->shGT = Fn; }
            Fn = Fb;
        }
    }
    __syncthreads();

    int B = ws->shB;
    int kn = 40 - (int)ws->shGT;
    unsigned lo = (unsigned)B << 21;
    unsigned hi = lo | 0x1FFFFFu;

    // compaction: strictly-above emit; in-bucket candidates to tlist
#pragma unroll
    for (int j = 0; j < 4; j++) {
        int m = kmap(tid, j, map_mode);
        unsigned k2 = key[j];
        if (k2 > hi) {
            int slot = atomicAdd(&ws->outcnt, 1);
            IDX[row * 40 + slot] = m;
        } else if (k2 >= lo) {
            int t2 = atomicAdd(&ws->tiecnt, 1);
            ws->tlist[t2] = ((unsigned long long)k2 << 32) | (unsigned)(2047 - m);
        }
    }
    __syncthreads();

    int tt = ws->tiecnt;
    for (int p = tid; p < tt; p += 256) {
        unsigned long long me = ws->tlist[p];
        int rk = 0;
        for (int q = 0; q < tt; q++) rk += (ws->tlist[q] > me);
        if (rk < kn) {
            int slot = atomicAdd(&ws->outcnt, 1);
            IDX[row * 40 + slot] = 2047 - (int)(me & 0xFFFFFFFFull);
        }
    }
}

// ---------------- top-40 from dist array (layers 1-3) ------------------------
__global__ void __launch_bounds__(256)
topk40_kernel(const float* __restrict__ S, int* __restrict__ IDX)
{
    __shared__ TopkWs ws;
    int row = blockIdx.x;
    const float* s = S + (long long)row * 1024;
    int tid = threadIdx.x;

    unsigned key[4];
    {
        float4 v = ((const float4*)s)[tid];
        key[0] = encf(v.x); key[1] = encf(v.y);
        key[2] = encf(v.z); key[3] = encf(v.w);
    }
    topk_select(key, &ws, row, IDX, 0);
}

// ---------------- layer-0 fused distance + top-40 ----------------------------
// dist bit-identical to the sgemm path: acc = fma chain; v = (2*acc - sq_r) - sq_m.
__global__ void __launch_bounds__(256)
topk40_l0(const float* __restrict__ X, const float* __restrict__ SQ,
          int* __restrict__ IDX)
{
    __shared__ TopkWs ws;
    __shared__ float sx[1024], sy[1024], sz[1024], ss[1024];

    int row = blockIdx.x;
    int b = row >> 10, r = row & 1023;
    int tid = threadIdx.x;

    const float* xb = X + (size_t)b * 1024 * 3;
#pragma unroll
    for (int it = 0; it < 4; it++) {
        int p = tid + 256 * it;
        sx[p] = xb[3 * p];
        sy[p] = xb[3 * p + 1];
        sz[p] = xb[3 * p + 2];
        ss[p] = SQ[b * 1024 + p];
    }
    __syncthreads();

    float xr = sx[r], yr = sy[r], zr = sz[r], sr = ss[r];
    unsigned key[4];
#pragma unroll
    for (int j = 0; j < 4; j++) {
        int m = tid + 256 * j;
        float acc = 0.f;
        acc = fmaf(xr, sx[m], acc);
        acc = fmaf(yr, sy[m], acc);
        acc = fmaf(zr, sz[m], acc);
        float v = (2.f * acc - sr) - ss[m];
        key[j] = encf(v);
    }
    topk_select(key, &ws, row, IDX, 1);
}

// ---------------- weight transform (all 4 layers, one launch) ---------------
__global__ void wprep_all(const float* __restrict__ W0, const float* __restrict__ W1,
                          const float* __restrict__ W2, const float* __restrict__ W3,
                          float* __restrict__ WPQ)
{
    int i = blockIdx.x * blockDim.x + threadIdx.x;
    const int n0 = 64 * 3, n1 = 64 * 64, n2 = 128 * 64, n3 = 256 * 128;
    const float* W; int Co, C, off;
    if (i < n0)                { W = W0; Co = 64;  C = 3;   off = 0;     }
    else if ((i -= n0) < n1)   { W = W1; Co = 64;  C = 64;  off = 1024;  }
    else if ((i -= n1) < n2)   { W = W2; Co = 128; C = 64;  off = 9216;  }
    else if ((i -= n2) < n3)   { W = W3; Co = 256; C = 128; off = 25600; }
    else return;
    int o = i / C, c = i % C;
    float wl = W[o * 2 * C + c];
    float wr = W[o * 2 * C + C + c];
    WPQ[off + o * C + c] = wl;
    WPQ[off + (Co + o) * C + c] = wr - wl;
}

// ---------------- gather-max + fused sq + fp16-split outputs ----------------
__global__ void __launch_bounds__(128)
edge_gathermax(const float* __restrict__ PQ,
               const int* __restrict__ IDX,
               const float* __restrict__ g,
               const float* __restrict__ bb,
               uint32_t* __restrict__ AH, uint32_t* __restrict__ AL,
               uint32_t* __restrict__ CH, uint32_t* __restrict__ CL,
               float* __restrict__ SQ,
               int Co, int cwoff, int write_sq, int write_a)
{
    const float BN_INV = 0.9999950000374997f;
    const int c4n = Co >> 2;
    const int G = 128 / c4n;
    const int pbase = blockIdx.x * G;

    __shared__ int nb[8 * 40];
    for (int i = threadIdx.x; i < G * 40; i += 128)
        nb[i] = IDX[(pbase + i / 40) * 40 + (i % 40)];
    __syncthreads();

    const int p = threadIdx.x / c4n;
    const int o = (threadIdx.x - p * c4n) * 4;
    const int pt = pbase + p;
    const int b = pt >> 10;
    const int ld = 2 * Co;
    const float* base = PQ + (size_t)(b << 10) * ld + o;
    const int* nbp = nb + p * 40;

    float4 mx = make_float4(-CUDART_INF_F, -CUDART_INF_F, -CUDART_INF_F, -CUDART_INF_F);
    float4 mn = make_float4(CUDART_INF_F, CUDART_INF_F, CUDART_INF_F, CUDART_INF_F);
#pragma unroll 8
    for (int k = 0; k < 40; k++) {
        float4 v = *(const float4*)(base + (size_t)nbp[k] * ld);
        mx.x = fmaxf(mx.x, v.x); mn.x = fminf(mn.x, v.x);
        mx.y = fmaxf(mx.y, v.y); mn.y = fminf(mn.y, v.y);
        mx.z = fmaxf(mx.z, v.z); mn.z = fminf(mn.z, v.z);
        mx.w = fmaxf(mx.w, v.w); mn.w = fminf(mn.w, v.w);
    }
    float4 q  = *(const float4*)&PQ[(size_t)pt * ld + Co + o];
    float4 gg = *(const float4*)&g[o];
    float4 bv = *(const float4*)&bb[o];

    float4 y;
    y.x = (gg.x >= 0.f ? mx.x : mn.x) + q.x;
    y.y = (gg.y >= 0.f ? mx.y : mn.y) + q.y;
    y.z = (gg.z >= 0.f ? mx.z : mn.z) + q.z;
    y.w = (gg.w >= 0.f ? mx.w : mn.w) + q.w;
    y.x = gg.x * (y.x * BN_INV) + bv.x;
    y.y = gg.y * (y.y * BN_INV) + bv.y;
    y.z = gg.z * (y.z * BN_INV) + bv.z;
    y.w = gg.w * (y.w * BN_INV) + bv.w;
    y.x = y.x > 0.f ? y.x : 0.2f * y.x;
    y.y = y.y > 0.f ? y.y : 0.2f * y.y;
    y.z = y.z > 0.f ? y.z : 0.2f * y.z;
    y.w = y.w > 0.f ? y.w : 0.2f * y.w;

    uint2 h, l;
    hsplit2(y.x, y.y, h.x, l.x);
    hsplit2(y.z, y.w, h.y, l.y);
    const int ow = o >> 1;
    const int Cw = Co >> 1;
    if (write_a) {
        *(uint2*)&AH[(size_t)pt * Cw + ow] = h;
        *(uint2*)&AL[(size_t)pt * Cw + ow] = l;
    }
    *(uint2*)&CH[(size_t)pt * 256 + cwoff + ow] = h;
    *(uint2*)&CL[(size_t)pt * 256 + cwoff + ow] = l;

    if (write_sq) {
        float s = y.x * y.x + y.y * y.y + y.z * y.z + y.w * y.w;
        for (int off = c4n >> 1; off >= 1; off >>= 1)
            s += __shfl_xor_sync(0xffffffffu, s, off);
        if ((threadIdx.x & (c4n - 1)) == 0) SQ[pt] = s;
    }
}

// ---------------- gmax init / decode ----------------------------------------
__global__ void gmax_init(unsigned* __restrict__ g)
{
    g[blockIdx.x * 1024 + threadIdx.x] = 0u;
}

__global__ void decode_out(const unsigned* __restrict__ g,
                           const float* __restrict__ bf, float* __restrict__ out)
{
    int i = blockIdx.x * 256 + threadIdx.x;
    unsigned e = g[i];
    unsigned u = (e & 0x80000000u) ? (e ^ 0x80000000u) : ~e;
    out[i] = __uint_as_float(u) + bf[i & 1023];
}

// ---------------- launch -----------------------------------------------------
extern "C" void kernel_launch(void* const* d_in, const int* in_sizes, int n_in,
                              void* d_out, int out_size)
{
    (void)in_sizes; (void)n_in; (void)out_size;
    const float* x  = (const float*)d_in[0];
    const float* w[4]  = {(const float*)d_in[1], (const float*)d_in[4],
                          (const float*)d_in[7], (const float*)d_in[10]};
    const float* g[4]  = {(const float*)d_in[2], (const float*)d_in[5],
                          (const float*)d_in[8], (const float*)d_in[11]};
    const float* bb[4] = {(const float*)d_in[3], (const float*)d_in[6],
                          (const float*)d_in[9], (const float*)d_in[12]};
    const float* wf = (const float*)d_in[13];
    const float* bf = (const float*)d_in[14];
    float* out = (float*)d_out;

    float *dist, *sq, *pq, *wpq; int* idx; unsigned* gm;
    uint32_t *ah, *al, *wh, *wl, *fh, *fl, *chp, *clp;
    cudaGetSymbolAddress((void**)&dist, d_dist);
    cudaGetSymbolAddress((void**)&sq,   d_sq);
    cudaGetSymbolAddress((void**)&idx,  d_idx);
    cudaGetSymbolAddress((void**)&pq,   d_pq);
    cudaGetSymbolAddress((void**)&wpq,  d_wpq);
    cudaGetSymbolAddress((void**)&gm,   d_gmax);
    cudaGetSymbolAddress((void**)&ah,   d_ah);
    cudaGetSymbolAddress((void**)&al,   d_al);
    cudaGetSymbolAddress((void**)&wh,   d_wh);
    cudaGetSymbolAddress((void**)&wl,   d_wl);
    cudaGetSymbolAddress((void**)&fh,   d_fh);
    cudaGetSymbolAddress((void**)&fl,   d_fl);
    cudaGetSymbolAddress((void**)&chp,  d_ch);
    cudaGetSymbolAddress((void**)&clp,  d_cl);

    cudaFuncSetAttribute(hgemm, cudaFuncAttributeMaxDynamicSharedMemorySize,
                         HSMEM);

    const int woffw[4] = {0, 512, 4608, 12800};
    const int offs[4]  = {0, 64, 128, 256};
    const int Cs[4]    = {3, 64, 64, 128};
    const int Cos[4]   = {64, 64, 128, 256};

    // launch order: #4 = topk40_l0 (profiled slot)
    wprep_all<<<(45248 + 255) / 256, 256>>>(w[0], w[1], w[2], w[3], wpq);
    gmax_init<<<16, 1024>>>(gm);
    sq_kernel<<<2048, 256>>>(x, 3, 3, sq);
    topk40_l0<<<16384, 256>>>(x, sq, idx);                 // fused dist+topk, l0
    cvt1d_h<<<(92160 / 4 + 255) / 256, 256>>>(wpq, wh, wl, 92160 / 4);
    cvt1d_h<<<(1024 * 512 / 4 + 255) / 256, 256>>>(wf, fh, fl, 1024 * 512 / 4);
    sgemm128<<<dim3(128, 1, 1), 256>>>(
        x, 3, 0, wpq, 3, 0, nullptr,
        pq, 128, 0, 16384, 128, 3, 0);
    edge_gathermax<<<2048, 128>>>(pq, idx, g[0], bb[0],
                                  ah, al, chp, clp, sq,
                                  64, offs[0] / 2, 1, 1);

    // layers 1-3 on tensor cores (fp16x3)
    for (int l = 1; l < 4; l++) {
        int C = Cs[l], Co = Cos[l];
        int Cw = C >> 1;

        hgemm<<<dim3(36, 1, 16), 256, HSMEM>>>(
            ah, al, Cw, 1024LL * Cw, nullptr, nullptr, 0, sq,
            dist, 1024, 1024LL * 1024, 1024, C, 1, nullptr);
        topk40_kernel<<<16384, 256>>>(dist, idx);
        hgemm<<<dim3(128, (2 * Co) / 128, 1), 256, HSMEM>>>(
            ah, al, Cw, 0, wh + woffw[l], wl + woffw[l], Cw, nullptr,
            pq, 2 * Co, 0, 2 * Co, C, 0, nullptr);
        edge_gathermax<<<16384 * Co / 512, 128>>>(pq, idx, g[l], bb[l],
                                                  ah, al, chp, clp, sq,
                                                  Co, offs[l] / 2,
                                                  (l < 3) ? 1 : 0,
                                                  (l < 3) ? 1 : 0);
    }

    // final linear 512 -> 1024 (fp16x3, fused max over N)
    hgemm<<<dim3(128, 8, 1), 256, HSMEM>>>(
        chp, clp, 256, 0, fh, fl, 256, nullptr,
        dist, 0, 0, 1024, 512, 2, gm);
    decode_out<<<64, 256>>>(gm, bf, out);
}

// round 17
// speedup vs baseline: 1.0393x; 1.0000x over previous
#include <cuda_runtime.h>
#include <cuda_fp16.h>
#include <math_constants.h>
#include <cstdint>

// ---------------- scratch (static device globals; no allocation) ------------
__device__ float    d_dist[16 * 1024 * 1024];
__device__ float    d_sq  [16 * 1024];
__device__ int      d_idx [16 * 1024 * 40];
__device__ float    d_pq  [16 * 1024 * 512];
__device__ float    d_wpq [92160];
__device__ unsigned d_gmax[16 * 1024];
// fp16-split planes (packed half2 words, k-pairs)
__device__ uint32_t d_ah[16 * 1024 * 64], d_al[16 * 1024 * 64];   // layer input (C<=128)
__device__ uint32_t d_wh[46080],          d_wl[46080];            // wpq
__device__ uint32_t d_fh[1024 * 256],     d_fl[1024 * 256];       // wf
__device__ uint32_t d_ch[16 * 1024 * 256], d_cl[16 * 1024 * 256]; // full cat

static __device__ __forceinline__ unsigned encf(float v) {
    unsigned u = __float_as_uint(v);
    return (u & 0x80000000u) ? ~u : (u | 0x80000000u);
}
static __device__ __forceinline__ void hsplit2(float a, float b,
                                               uint32_t& h, uint32_t& l) {
    __half ha = __float2half_rn(a), hb = __float2half_rn(b);
    __half la = __float2half_rn(a - __half2float(ha));
    __half lb = __float2half_rn(b - __half2float(hb));
    __half2 H = __halves2half2(ha, hb), L = __halves2half2(la, lb);
    h = *(uint32_t*)&H;
    l = *(uint32_t*)&L;
}
static __device__ __forceinline__ void mma_f16(float* c, uint32_t a0, uint32_t a1,
                                               uint32_t a2, uint32_t a3,
                                               uint32_t b0, uint32_t b1) {
    asm volatile(
        "mma.sync.aligned.m16n8k16.row.col.f32.f16.f16.f32 "
        "{%0,%1,%2,%3}, {%4,%5,%6,%7}, {%8,%9}, {%0,%1,%2,%3};"
        : "+f"(c[0]), "+f"(c[1]), "+f"(c[2]), "+f"(c[3])
        : "r"(a0), "r"(a1), "r"(a2), "r"(a3), "r"(b0), "r"(b1));
}

static constexpr int KSW   = 128 * 12;
static constexpr int PLW   = 2 * KSW;
static constexpr int HSMEM = 4 * PLW * 4;   // 49152 bytes

// ---------------- weight conversion ------------------------------------------
__global__ void cvt1d_h(const float* __restrict__ src, uint32_t* __restrict__ hi,
                        uint32_t* __restrict__ lo, int n4)
{
    int i = blockIdx.x * 256 + threadIdx.x;
    if (i >= n4) return;
    float4 v = ((const float4*)src)[i];
    uint2 h, l;
    hsplit2(v.x, v.y, h.x, l.x);
    hsplit2(v.z, v.w, h.y, l.y);
    ((uint2*)hi)[i] = h;
    ((uint2*)lo)[i] = l;
}

// ============ fp16x3 tensor GEMM: C = A(..xK) * B(NxK)^T ====================
__global__ void __launch_bounds__(256, 2)
hgemm(const uint32_t* __restrict__ Ah, const uint32_t* __restrict__ Al,
      int ldaw, long long sA,
      const uint32_t* __restrict__ Bh, const uint32_t* __restrict__ Bl,
      int ldbw,
      const float* __restrict__ sq,
      float* __restrict__ C, int ldc, long long sC,
      int N, int K, int mode, unsigned* __restrict__ gmax)
{
    extern __shared__ uint32_t dsm[];
    uint32_t* sAh = dsm;
    uint32_t* sAl = sAh + PLW;
    uint32_t* sBh = sAl + PLW;
    uint32_t* sBl = sBh + PLW;

    int bz = blockIdx.z;
    Ah += (long long)bz * sA;
    Al += (long long)bz * sA;
    const float* sqb = sq ? sq + (long long)bz * 1024 : nullptr;
    C += (long long)bz * sC;

    int bi, bj;
    if (mode == 1) {
        int nb = N >> 7;
        int p = blockIdx.x;
        bi = 0;
        while (p >= nb - bi) { p -= nb - bi; bi++; }
        bj = bi + p;
    } else { bi = blockIdx.x; bj = blockIdx.y; }
    const int row0 = bi * 128, col0 = bj * 128;

    const uint32_t* Bh2 = (mode == 1) ? Ah : Bh;
    const uint32_t* Bl2 = (mode == 1) ? Al : Bl;
    const int ldb2 = (mode == 1) ? ldaw : ldbw;

    const int tid = threadIdx.x;
    const int wid = tid >> 5, lane = tid & 31;
    const int wr = wid >> 2, wc = wid & 3;
    const int g = lane >> 2, t = lane & 3;

    float acc[4][4][4];
#pragma unroll
    for (int mt = 0; mt < 4; mt++)
#pragma unroll
        for (int nt = 0; nt < 4; nt++)
#pragma unroll
            for (int i = 0; i < 4; i++) acc[mt][nt][i] = 0.f;

    int lrow[2], lw4[2], lso[2];
    size_t loa[2], lob[2];
#pragma unroll
    for (int i = 0; i < 2; i++) {
        int id4 = i * 256 + tid;
        lrow[i] = id4 >> 2;
        lw4[i] = id4 & 3;
        int ks = lw4[i] >> 1, wi = (lw4[i] & 1) * 4;
        lso[i] = ks * KSW + lrow[i] * 12 + wi;
        loa[i] = (size_t)(row0 + lrow[i]) * ldaw + lw4[i] * 4;
        lob[i] = (size_t)(col0 + lrow[i]) * ldb2 + lw4[i] * 4;
    }

    uint4 pah[2], pal[2], pbh[2], pbl[2];
    const int nch = K >> 5;

#pragma unroll
    for (int i = 0; i < 2; i++) {
        pah[i] = *(const uint4*)&Ah[loa[i]];
        pal[i] = *(const uint4*)&Al[loa[i]];
        pbh[i] = *(const uint4*)&Bh2[lob[i]];
        pbl[i] = *(const uint4*)&Bl2[lob[i]];
    }
#pragma unroll
    for (int i = 0; i < 2; i++) {
        *(uint4*)&sAh[lso[i]] = pah[i];
        *(uint4*)&sAl[lso[i]] = pal[i];
        *(uint4*)&sBh[lso[i]] = pbh[i];
        *(uint4*)&sBl[lso[i]] = pbl[i];
    }
    __syncthreads();

    for (int ch = 0; ch < nch; ch++) {
        if (ch + 1 < nch) {
            const int k1 = (ch + 1) * 16;
#pragma unroll
            for (int i = 0; i < 2; i++) {
                pah[i] = *(const uint4*)&Ah[loa[i] + k1];
                pal[i] = *(const uint4*)&Al[loa[i] + k1];
                pbh[i] = *(const uint4*)&Bh2[lob[i] + k1];
                pbl[i] = *(const uint4*)&Bl2[lob[i] + k1];
            }
        }

#pragma unroll
        for (int ks = 0; ks < 2; ks++) {
            const uint32_t* pAh = sAh + ks * KSW;
            const uint32_t* pAl = sAl + ks * KSW;
            const uint32_t* pBh = sBh + ks * KSW;
            const uint32_t* pBl = sBl + ks * KSW;

            uint32_t bh0[4], bh1[4], bl0[4], bl1[4];
#pragma unroll
            for (int nt = 0; nt < 4; nt++) {
                int nb_ = wc * 32 + nt * 8 + g;
                bh0[nt] = pBh[nb_ * 12 + t];
                bh1[nt] = pBh[nb_ * 12 + 4 + t];
                bl0[nt] = pBl[nb_ * 12 + t];
                bl1[nt] = pBl[nb_ * 12 + 4 + t];
            }
            uint32_t a[4][4];
#pragma unroll
            for (int mt = 0; mt < 4; mt++) {
                int rb = wr * 64 + mt * 16 + g;
                a[mt][0] = pAh[rb * 12 + t];
                a[mt][1] = pAh[(rb + 8) * 12 + t];
                a[mt][2] = pAh[rb * 12 + 4 + t];
                a[mt][3] = pAh[(rb + 8) * 12 + 4 + t];
            }
#pragma unroll
            for (int nt = 0; nt < 4; nt++)
#pragma unroll
                for (int mt = 0; mt < 4; mt++) {
                    mma_f16(acc[mt][nt], a[mt][0], a[mt][1], a[mt][2], a[mt][3],
                            bh0[nt], bh1[nt]);
                    mma_f16(acc[mt][nt], a[mt][0], a[mt][1], a[mt][2], a[mt][3],
                            bl0[nt], bl1[nt]);
                }
#pragma unroll
            for (int mt = 0; mt < 4; mt++) {
                int rb = wr * 64 + mt * 16 + g;
                a[mt][0] = pAl[rb * 12 + t];
                a[mt][1] = pAl[(rb + 8) * 12 + t];
                a[mt][2] = pAl[rb * 12 + 4 + t];
                a[mt][3] = pAl[(rb + 8) * 12 + 4 + t];
            }
#pragma unroll
            for (int nt = 0; nt < 4; nt++)
#pragma unroll
                for (int mt = 0; mt < 4; mt++)
                    mma_f16(acc[mt][nt], a[mt][0], a[mt][1], a[mt][2], a[mt][3],
                            bh0[nt], bh1[nt]);
        }
        __syncthreads();
        if (ch + 1 < nch) {
#pragma unroll
            for (int i = 0; i < 2; i++) {
                *(uint4*)&sAh[lso[i]] = pah[i];
                *(uint4*)&sAl[lso[i]] = pal[i];
                *(uint4*)&sBh[lso[i]] = pbh[i];
                *(uint4*)&sBl[lso[i]] = pbl[i];
            }
            __syncthreads();
        }
    }

    if (mode == 2) {
        const int batch = row0 >> 10;
#pragma unroll
        for (int nt = 0; nt < 4; nt++)
#pragma unroll
            for (int j = 0; j < 2; j++) {
                float v = -CUDART_INF_F;
#pragma unroll
                for (int mt = 0; mt < 4; mt++)
                    v = fmaxf(v, fmaxf(acc[mt][nt][j], acc[mt][nt][j + 2]));
#pragma unroll
                for (int off = 4; off < 32; off <<= 1)
                    v = fmaxf(v, __shfl_xor_sync(0xffffffffu, v, off));
                if (lane < 4) {
                    int col = col0 + wc * 32 + nt * 8 + 2 * lane + j;
                    atomicMax(&gmax[batch * 1024 + col], encf(v));
                }
            }
        return;
    }

#pragma unroll
    for (int mt = 0; mt < 4; mt++)
#pragma unroll
        for (int nt = 0; nt < 4; nt++) {
            int r = row0 + wr * 64 + mt * 16 + g;
            int c = col0 + wc * 32 + nt * 8 + 2 * t;
            float v0 = acc[mt][nt][0], v1 = acc[mt][nt][1];
            float v2 = acc[mt][nt][2], v3 = acc[mt][nt][3];
            if (mode == 1) {
                float sr0 = sqb[r & 1023], sr8 = sqb[(r + 8) & 1023];
                float sc0 = sqb[c & 1023], sc1 = sqb[(c + 1) & 1023];
                v0 = 2.f * v0 - sr0 - sc0; v1 = 2.f * v1 - sr0 - sc1;
                v2 = 2.f * v2 - sr8 - sc0; v3 = 2.f * v3 - sr8 - sc1;
            }
            *(float2*)&C[(size_t)r * ldc + c] = make_float2(v0, v1);
            *(float2*)&C[(size_t)(r + 8) * ldc + c] = make_float2(v2, v3);
            if (mode == 1 && bi != bj) {
                C[(size_t)c * ldc + r] = v0;
                C[(size_t)(c + 1) * ldc + r] = v1;
                C[(size_t)c * ldc + r + 8] = v2;
                C[(size_t)(c + 1) * ldc + r + 8] = v3;
            }
        }
}

// ---------------- 128x128x8 FFMA SGEMM (layer 0 pq only, K=3) --------------
__global__ void __launch_bounds__(256, 2)
sgemm128(const float* __restrict__ A, int lda, long long sA,
         const float* __restrict__ B, int ldb, long long sB,
         const float* __restrict__ sq,
         float* __restrict__ C, int ldc, long long sC,
         int M, int N, int K, int mode)
{
    int bz = blockIdx.z;
    A += (long long)bz * sA;
    B += (long long)bz * sB;
    C += (long long)bz * sC;
    const float* sqb = sq ? (sq + (long long)bz * M) : nullptr;

    int bi, bj;
    if (mode == 1) {
        int nb = N >> 7;
        int p = blockIdx.x;
        bi = 0;
        while (p >= nb - bi) { p -= nb - bi; bi++; }
        bj = bi + p;
    } else { bi = blockIdx.x; bj = blockIdx.y; }
    const int row0 = bi * 128;
    const int col0 = bj * 128;

    __shared__ float As[2][8][132];
    __shared__ float Bs[2][8][132];

    const int tid = threadIdx.x;
    const int lk = tid & 7;
    const int lm = tid >> 3;
    const int tx = tid & 15;
    const int ty = tid >> 4;

    float acc[8][8];
#pragma unroll
    for (int i = 0; i < 8; i++)
#pragma unroll
        for (int j = 0; j < 8; j++) acc[i][j] = 0.f;

    float pa[4], pb[4];
    const int nk = (K + 7) >> 3;

    {
        int k = lk;
        bool ok = (k < K);
#pragma unroll
        for (int j = 0; j < 4; j++) {
            int m = lm + 32 * j;
            pa[j] = ok ? A[(long long)(row0 + m) * lda + k] : 0.f;
            pb[j] = ok ? B[(long long)(col0 + m) * ldb + k] : 0.f;
        }
#pragma unroll
        for (int j = 0; j < 4; j++) {
            As[0][lk][lm + 32 * j] = pa[j];
            Bs[0][lk][lm + 32 * j] = pb[j];
        }
    }
    __syncthreads();

    for (int t = 0; t < nk; t++) {
        int cur = t & 1;
        if (t + 1 < nk) {
            int k = (t + 1) * 8 + lk;
            bool ok = (k < K);
#pragma unroll
            for (int j = 0; j < 4; j++) {
                int m = lm + 32 * j;
                pa[j] = ok ? A[(long long)(row0 + m) * lda + k] : 0.f;
                pb[j] = ok ? B[(long long)(col0 + m) * ldb + k] : 0.f;
            }
        }
#pragma unroll
        for (int kk = 0; kk < 8; kk++) {
            float a[8], b[8];
            *(float4*)&a[0] = *(const float4*)&As[cur][kk][ty * 4];
            *(float4*)&a[4] = *(const float4*)&As[cur][kk][64 + ty * 4];
            *(float4*)&b[0] = *(const float4*)&Bs[cur][kk][tx * 4];
            *(float4*)&b[4] = *(const float4*)&Bs[cur][kk][64 + tx * 4];
#pragma unroll
            for (int i = 0; i < 8; i++)
#pragma unroll
                for (int j = 0; j < 8; j++)
                    acc[i][j] += a[i] * b[j];
        }
        if (t + 1 < nk) {
            int nxt = cur ^ 1;
#pragma unroll
            for (int j = 0; j < 4; j++) {
                As[nxt][lk][lm + 32 * j] = pa[j];
                Bs[nxt][lk][lm + 32 * j] = pb[j];
            }
        }
        __syncthreads();
    }

#pragma unroll
    for (int ih = 0; ih < 2; ih++) {
#pragma unroll
        for (int i = 0; i < 4; i++) {
            int r = row0 + ih * 64 + ty * 4 + i;
            float srow = (mode == 1) ? sqb[r] : 0.f;
#pragma unroll
            for (int jh = 0; jh < 2; jh++) {
                float outv[4];
#pragma unroll
                for (int j = 0; j < 4; j++) {
                    float v = acc[ih * 4 + i][jh * 4 + j];
                    if (mode == 1)
                        v = (2.f * v - srow) - sqb[col0 + jh * 64 + tx * 4 + j];
                    outv[j] = v;
                }
                *(float4*)&C[(long long)r * ldc + col0 + jh * 64 + tx * 4] =
                    *(float4*)&outv[0];
            }
        }
    }

    if (mode == 1 && bi != bj) {
#pragma unroll
        for (int jh = 0; jh < 2; jh++)
#pragma unroll
            for (int j = 0; j < 4; j++) {
                int c = col0 + jh * 64 + tx * 4 + j;
                float sc = sqb[c];
#pragma unroll
                for (int ih = 0; ih < 2; ih++) {
                    int rb = row0 + ih * 64 + ty * 4;
                    float mv[4];
#pragma unroll
                    for (int i = 0; i < 4; i++)
                        mv[i] = (2.f * acc[ih * 4 + i][jh * 4 + j] - sqb[rb + i]) - sc;
                    *(float4*)&C[(long long)c * ldc + rb] = *(float4*)&mv[0];
                }
            }
    }
}

// ---------------- squared norms (layer 0 input x only) -----------------------
__global__ void sq_kernel(const float* __restrict__ H, int lda, int C,
                          float* __restrict__ SQ)
{
    int gwarp = (blockIdx.x * blockDim.x + threadIdx.x) >> 5;
    int lane = threadIdx.x & 31;
    if (gwarp >= 16 * 1024) return;
    const float* h = H + (long long)gwarp * lda;
    float s = 0.f;
    for (int c = lane; c < C; c += 32) { float v = h[c]; s += v * v; }
#pragma unroll
    for (int d = 16; d > 0; d >>= 1) s += __shfl_down_sync(0xffffffffu, s, d);
    if (lane == 0) SQ[gwarp] = s;
}

// ---------------- top-40: single-level 2048-bin radix, overlaid smem --------
// Phase overlay in buf[4096]: (l0 phase 1) xyz/ss staging; (phase 2) hist in
// words [0,2048), tlist (u64) in words [2048,4096). map_mode 0: m = tid*4+j;
// 1: m = tid + 256*j.
struct TopkWs {
    uint32_t buf[4096];
    unsigned cs[256];
    unsigned wsum[8];
    int shB;
    unsigned shGT;
    int outcnt, tiecnt;
};

static __device__ __forceinline__ int kmap(int tid, int j, int map_mode) {
    return map_mode ? (tid + 256 * j) : (tid * 4 + j);
}

static __device__ void topk_select(unsigned key[4], TopkWs* ws,
                                   int row, int* __restrict__ IDX, int map_mode)
{
    int tid = threadIdx.x;
    int lane = tid & 31, w = tid >> 5;
    unsigned* hist = ws->buf;
    unsigned long long* tlist = (unsigned long long*)(ws->buf + 2048);

    // zero hist + counters (overwrites phase-1 staging; caller synced)
#pragma unroll
    for (int j = 0; j < 8; j++) hist[tid + 256 * j] = 0;
    if (tid == 0) { ws->outcnt = 0; ws->tiecnt = 0; }
    __syncthreads();

    // 11-bit histogram
#pragma unroll
    for (int j = 0; j < 4; j++)
        atomicAdd(&hist[key[j] >> 21], 1u);
    __syncthreads();

    // local suffix over owned chunk [8*tid, 8*tid+8)
    uint4 h0 = *(const uint4*)&hist[tid * 8];
    uint4 h1 = *(const uint4*)&hist[tid * 8 + 4];
    unsigned hh[8] = {h0.x, h0.y, h0.z, h0.w, h1.x, h1.y, h1.z, h1.w};
    unsigned suf[8];
    unsigned tot = 0;
#pragma unroll
    for (int j = 7; j >= 0; j--) { tot += hh[j]; suf[j] = tot; }

    ws->cs[tid] = tot;
    __syncthreads();

    // inclusive suffix over 256 chunk totals
    unsigned v = ws->cs[255 - tid];
#pragma unroll
    for (int d = 1; d < 32; d <<= 1) {
        unsigned n = __shfl_up_sync(0xffffffffu, v, d);
        if (lane >= d) v += n;
    }
    if (lane == 31) ws->wsum[w] = v;
    __syncthreads();
    if (tid == 0) {
        unsigned a = 0;
#pragma unroll
        for (int q = 0; q < 8; q++) { unsigned t2 = ws->wsum[q]; ws->wsum[q] = a; a += t2; }
    }
    __syncthreads();
    unsigned inc = v + ws->wsum[w];
    ws->cs[255 - tid] = inc;
    __syncthreads();

    // boundary bin B: F(B) >= 40 > F(B+1)
    {
        unsigned ex = ws->cs[tid] - tot;
        unsigned Fn = ex;
#pragma unroll
        for (int j = 7; j >= 0; j--) {
            unsigned Fb = suf[j] + ex;
            if (Fb >= 40u && Fn < 40u) { ws->shB = tid * 8 + j; ws->shGT = Fn; }
            Fn = Fb;
        }
    }
    __syncthreads();

    int B = ws->shB;
    int kn = 40 - (int)ws->shGT;
    unsigned lo = (unsigned)B << 21;
    unsigned hi = lo | 0x1FFFFFu;

    // compaction: strictly-above emit; in-bucket candidates to tlist
    // (tlist occupies buf[2048..4096); hist is dead past this point)
#pragma unroll
    for (int j = 0; j < 4; j++) {
        int m = kmap(tid, j, map_mode);
        unsigned k2 = key[j];
        if (k2 > hi) {
            int slot = atomicAdd(&ws->outcnt, 1);
            IDX[row * 40 + slot] = m;
        } else if (k2 >= lo) {
            int t2 = atomicAdd(&ws->tiecnt, 1);
            tlist[t2] = ((unsigned long long)k2 << 32) | (unsigned)(2047 - m);
        }
    }
    __syncthreads();

    int tt = ws->tiecnt;
    for (int p = tid; p < tt; p += 256) {
        unsigned long long me = tlist[p];
        int rk = 0;
        for (int q = 0; q < tt; q++) rk += (tlist[q] > me);
        if (rk < kn) {
            int slot = atomicAdd(&ws->outcnt, 1);
            IDX[row * 40 + slot] = 2047 - (int)(me & 0xFFFFFFFFull);
        }
    }
}

// ---------------- top-40 from dist array (layers 1-3) ------------------------
__global__ void __launch_bounds__(256)
topk40_kernel(const float* __restrict__ S, int* __restrict__ IDX)
{
    __shared__ TopkWs ws;
    int row = blockIdx.x;
    const float* s = S + (long long)row * 1024;
    int tid = threadIdx.x;

    unsigned key[4];
    {
        float4 v = ((const float4*)s)[tid];
        key[0] = encf(v.x); key[1] = encf(v.y);
        key[2] = encf(v.z); key[3] = encf(v.w);
    }
    topk_select(key, &ws, row, IDX, 0);
}

// ---------------- layer-0 fused distance + top-40 ----------------------------
// dist bit-identical to the sgemm path: acc = fma chain; v = (2*acc - sq_r) - sq_m.
// xyz/ss staged in ws.buf (phase 1), then buf reused by topk_select (phase 2).
__global__ void __launch_bounds__(256)
topk40_l0(const float* __restrict__ X, const float* __restrict__ SQ,
          int* __restrict__ IDX)
{
    __shared__ TopkWs ws;
    float* sx = (float*)ws.buf;
    float* sy = sx + 1024;
    float* sz = sy + 1024;
    float* ss = sz + 1024;

    int row = blockIdx.x;
    int b = row >> 10, r = row & 1023;
    int tid = threadIdx.x;

    const float* xb = X + (size_t)b * 1024 * 3;
#pragma unroll
    for (int it = 0; it < 4; it++) {
        int p = tid + 256 * it;
        sx[p] = xb[3 * p];
        sy[p] = xb[3 * p + 1];
        sz[p] = xb[3 * p + 2];
        ss[p] = SQ[b * 1024 + p];
    }
    __syncthreads();

    float xr = sx[r], yr = sy[r], zr = sz[r], sr = ss[r];
    unsigned key[4];
#pragma unroll
    for (int j = 0; j < 4; j++) {
        int m = tid + 256 * j;
        float acc = 0.f;
        acc = fmaf(xr, sx[m], acc);
        acc = fmaf(yr, sy[m], acc);
        acc = fmaf(zr, sz[m], acc);
        float v = (2.f * acc - sr) - ss[m];
        key[j] = encf(v);
    }
    __syncthreads();    // all xyz/ss reads done before buf is reused as hist
    topk_select(key, &ws, row, IDX, 1);
}

// ---------------- weight transform (all 4 layers, one launch) ---------------
__global__ void wprep_all(const float* __restrict__ W0, const float* __restrict__ W1,
                          const float* __restrict__ W2, const float* __restrict__ W3,
                          float* __restrict__ WPQ)
{
    int i = blockIdx.x * blockDim.x + threadIdx.x;
    const int n0 = 64 * 3, n1 = 64 * 64, n2 = 128 * 64, n3 = 256 * 128;
    const float* W; int Co, C, off;
    if (i < n0)                { W = W0; Co = 64;  C = 3;   off = 0;     }
    else if ((i -= n0) < n1)   { W = W1; Co = 64;  C = 64;  off = 1024;  }
    else if ((i -= n1) < n2)   { W = W2; Co = 128; C = 64;  off = 9216;  }
    else if ((i -= n2) < n3)   { W = W3; Co = 256; C = 128; off = 25600; }
    else return;
    int o = i / C, c = i % C;
    float wl = W[o * 2 * C + c];
    float wr = W[o * 2 * C + C + c];
    WPQ[off + o * C + c] = wl;
    WPQ[off + (Co + o) * C + c] = wr - wl;
}

// ---------------- gather-max + fused sq + fp16-split outputs ----------------
__global__ void __launch_bounds__(128)
edge_gathermax(const float* __restrict__ PQ,
               const int* __restrict__ IDX,
               const float* __restrict__ g,
               const float* __restrict__ bb,
               uint32_t* __restrict__ AH, uint32_t* __restrict__ AL,
               uint32_t* __restrict__ CH, uint32_t* __restrict__ CL,
               float* __restrict__ SQ,
               int Co, int cwoff, int write_sq, int write_a)
{
    const float BN_INV = 0.9999950000374997f;
    const int c4n = Co >> 2;
    const int G = 128 / c4n;
    const int pbase = blockIdx.x * G;

    __shared__ int nb[8 * 40];
    for (int i = threadIdx.x; i < G * 40; i += 128)
        nb[i] = IDX[(pbase + i / 40) * 40 + (i % 40)];
    __syncthreads();

    const int p = threadIdx.x / c4n;
    const int o = (threadIdx.x - p * c4n) * 4;
    const int pt = pbase + p;
    const int b = pt >> 10;
    const int ld = 2 * Co;
    const float* base = PQ + (size_t)(b << 10) * ld + o;
    const int* nbp = nb + p * 40;

    float4 mx = make_float4(-CUDART_INF_F, -CUDART_INF_F, -CUDART_INF_F, -CUDART_INF_F);
    float4 mn = make_float4(CUDART_INF_F, CUDART_INF_F, CUDART_INF_F, CUDART_INF_F);
#pragma unroll 8
    for (int k = 0; k < 40; k++) {
        float4 v = *(const float4*)(base + (size_t)nbp[k] * ld);
        mx.x = fmaxf(mx.x, v.x); mn.x = fminf(mn.x, v.x);
        mx.y = fmaxf(mx.y, v.y); mn.y = fminf(mn.y, v.y);
        mx.z = fmaxf(mx.z, v.z); mn.z = fminf(mn.z, v.z);
        mx.w = fmaxf(mx.w, v.w); mn.w = fminf(mn.w, v.w);
    }
    float4 q  = *(const float4*)&PQ[(size_t)pt * ld + Co + o];
    float4 gg = *(const float4*)&g[o];
    float4 bv = *(const float4*)&bb[o];

    float4 y;
    y.x = (gg.x >= 0.f ? mx.x : mn.x) + q.x;
    y.y = (gg.y >= 0.f ? mx.y : mn.y) + q.y;
    y.z = (gg.z >= 0.f ? mx.z : mn.z) + q.z;
    y.w = (gg.w >= 0.f ? mx.w : mn.w) + q.w;
    y.x = gg.x * (y.x * BN_INV) + bv.x;
    y.y = gg.y * (y.y * BN_INV) + bv.y;
    y.z = gg.z * (y.z * BN_INV) + bv.z;
    y.w = gg.w * (y.w * BN_INV) + bv.w;
    y.x = y.x > 0.f ? y.x : 0.2f * y.x;
    y.y = y.y > 0.f ? y.y : 0.2f * y.y;
    y.z = y.z > 0.f ? y.z : 0.2f * y.z;
    y.w = y.w > 0.f ? y.w : 0.2f * y.w;

    uint2 h, l;
    hsplit2(y.x, y.y, h.x, l.x);
    hsplit2(y.z, y.w, h.y, l.y);
    const int ow = o >> 1;
    const int Cw = Co >> 1;
    if (write_a) {
        *(uint2*)&AH[(size_t)pt * Cw + ow] = h;
        *(uint2*)&AL[(size_t)pt * Cw + ow] = l;
    }
    *(uint2*)&CH[(size_t)pt * 256 + cwoff + ow] = h;
    *(uint2*)&CL[(size_t)pt * 256 + cwoff + ow] = l;

    if (write_sq) {
        float s = y.x * y.x + y.y * y.y + y.z * y.z + y.w * y.w;
        for (int off = c4n >> 1; off >= 1; off >>= 1)
            s += __shfl_xor_sync(0xffffffffu, s, off);
        if ((threadIdx.x & (c4n - 1)) == 0) SQ[pt] = s;
    }
}

// ---------------- gmax init / decode ----------------------------------------
__global__ void gmax_init(unsigned* __restrict__ g)
{
    g[blockIdx.x * 1024 + threadIdx.x] = 0u;
}

__global__ void decode_out(const unsigned* __restrict__ g,
                           const float* __restrict__ bf, float* __restrict__ out)
{
    int i = blockIdx.x * 256 + threadIdx.x;
    unsigned e = g[i];
    unsigned u = (e & 0x80000000u) ? (e ^ 0x80000000u) : ~e;
    out[i] = __uint_as_float(u) + bf[i & 1023];
}

// ---------------- launch -----------------------------------------------------
extern "C" void kernel_launch(void* const* d_in, const int* in_sizes, int n_in,
                              void* d_out, int out_size)
{
    (void)in_sizes; (void)n_in; (void)out_size;
    const float* x  = (const float*)d_in[0];
    const float* w[4]  = {(const float*)d_in[1], (const float*)d_in[4],
                          (const float*)d_in[7], (const float*)d_in[10]};
    const float* g[4]  = {(const float*)d_in[2], (const float*)d_in[5],
                          (const float*)d_in[8], (const float*)d_in[11]};
    const float* bb[4] = {(const float*)d_in[3], (const float*)d_in[6],
                          (const float*)d_in[9], (const float*)d_in[12]};
    const float* wf = (const float*)d_in[13];
    const float* bf = (const float*)d_in[14];
    float* out = (float*)d_out;

    float *dist, *sq, *pq, *wpq; int* idx; unsigned* gm;
    uint32_t *ah, *al, *wh, *wl, *fh, *fl, *chp, *clp;
    cudaGetSymbolAddress((void**)&dist, d_dist);
    cudaGetSymbolAddress((void**)&sq,   d_sq);
    cudaGetSymbolAddress((void**)&idx,  d_idx);
    cudaGetSymbolAddress((void**)&pq,   d_pq);
    cudaGetSymbolAddress((void**)&wpq,  d_wpq);
    cudaGetSymbolAddress((void**)&gm,   d_gmax);
    cudaGetSymbolAddress((void**)&ah,   d_ah);
    cudaGetSymbolAddress((void**)&al,   d_al);
    cudaGetSymbolAddress((void**)&wh,   d_wh);
    cudaGetSymbolAddress((void**)&wl,   d_wl);
    cudaGetSymbolAddress((void**)&fh,   d_fh);
    cudaGetSymbolAddress((void**)&fl,   d_fl);
    cudaGetSymbolAddress((void**)&chp,  d_ch);
    cudaGetSymbolAddress((void**)&clp,  d_cl);

    cudaFuncSetAttribute(hgemm, cudaFuncAttributeMaxDynamicSharedMemorySize,
                         HSMEM);

    const int woffw[4] = {0, 512, 4608, 12800};
    const int offs[4]  = {0, 64, 128, 256};
    const int Cs[4]    = {3, 64, 64, 128};
    const int Cos[4]   = {64, 64, 128, 256};

    // launch order: #4 = topk40_l0 (profiled slot)
    wprep_all<<<(45248 + 255) / 256, 256>>>(w[0], w[1], w[2], w[3], wpq);
    gmax_init<<<16, 1024>>>(gm);
    sq_kernel<<<2048, 256>>>(x, 3, 3, sq);
    topk40_l0<<<16384, 256>>>(x, sq, idx);                 // fused dist+topk, l0
    cvt1d_h<<<(92160 / 4 + 255) / 256, 256>>>(wpq, wh, wl, 92160 / 4);
    cvt1d_h<<<(1024 * 512 / 4 + 255) / 256, 256>>>(wf, fh, fl, 1024 * 512 / 4);
    sgemm128<<<dim3(128, 1, 1), 256>>>(
        x, 3, 0, wpq, 3, 0, nullptr,
        pq, 128, 0, 16384, 128, 3, 0);
    edge_gathermax<<<2048, 128>>>(pq, idx, g[0], bb[0],
                                  ah, al, chp, clp, sq,
                                  64, offs[0] / 2, 1, 1);

    // layers 1-3 on tensor cores (fp16x3)
    for (int l = 1; l < 4; l++) {
        int C = Cs[l], Co = Cos[l];
        int Cw = C >> 1;

        hgemm<<<dim3(36, 1, 16), 256, HSMEM>>>(
            ah, al, Cw, 1024LL * Cw, nullptr, nullptr, 0, sq,
            dist, 1024, 1024LL * 1024, 1024, C, 1, nullptr);
        topk40_kernel<<<16384, 256>>>(dist, idx);
        hgemm<<<dim3(128, (2 * Co) / 128, 1), 256, HSMEM>>>(
            ah, al, Cw, 0, wh + woffw[l], wl + woffw[l], Cw, nullptr,
            pq, 2 * Co, 0, 2 * Co, C, 0, nullptr);
        edge_gathermax<<<16384 * Co / 512, 128>>>(pq, idx, g[l], bb[l],
                                                  ah, al, chp, clp, sq,
                                                  Co, offs[l] / 2,
                                                  (l < 3) ? 1 : 0,
                                                  (l < 3) ? 1 : 0);
    }

    // final linear 512 -> 1024 (fp16x3, fused max over N)
    hgemm<<<dim3(128, 8, 1), 256, HSMEM>>>(
        chp, clp, 256, 0, fh, fl, 256, nullptr,
        dist, 0, 0, 1024, 512, 2, gm);
    decode_out<<<64, 256>>>(gm, bf, out);
}